// round 3
// baseline (speedup 1.0000x reference)
#include <cuda_runtime.h>
#include <math.h>

#define NPTS 20000
#define KNN  16
#define C    256
#define G    16
#define EPS  1e-5f
#define P    4          // points per block in K2
#define BM   16         // feat rows per block in K1
#define CP   260        // padded row stride for hid

typedef unsigned long long ull;

// ---------------- f32x2 helpers ---------------------------------------------
__device__ __forceinline__ ull fma2(ull a, ull b, ull c) {
    ull d;
    asm("fma.rn.f32x2 %0, %1, %2, %3;" : "=l"(d) : "l"(a), "l"(b), "l"(c));
    return d;
}
__device__ __forceinline__ ull pack2(float x, float y) {
    ull r;
    asm("mov.b64 %0, {%1, %2};" : "=l"(r) : "f"(x), "f"(y));
    return r;
}
__device__ __forceinline__ float hsum2(ull v) {
    float x, y;
    asm("mov.b64 {%0, %1}, %2;" : "=f"(x), "=f"(y) : "l"(v));
    return x + y;
}
__device__ __forceinline__ float2 unpk2(ull v) {
    float2 r;
    asm("mov.b64 {%0, %1}, %2;" : "=f"(r.x), "=f"(r.y) : "l"(v));
    return r;
}

// ---------------- scratch (static device memory) ---------------------------
__device__ float g_vall[NPTS * C];
__device__ float g_qW[NPTS * G];
__device__ float g_kW[NPTS * G];
__device__ float g_A4[G * C];          // (Wp2@Ww1), k-interleaved [kb][g][4k]
__device__ float g_wp2t[C * C];        // Wp2^T: [c][k]
__device__ float g_wiq[C / 2 * C * 2]; // Wq k-pair interleaved [kp][c][2]
__device__ float g_wik[C / 2 * C * 2];
__device__ float g_wiv[C / 2 * C * 2];
__device__ float g_sq[C], g_tq[C];
__device__ float g_sk[C], g_tk[C];
__device__ float g_sp[C], g_tp[C];
__device__ float g_sw[G], g_cw[G];

// ---------------- prep kernels ---------------------------------------------
__global__ void prep_fold(const float* __restrict__ bq, const float* __restrict__ bnq,
                          const float* __restrict__ bk, const float* __restrict__ bnk,
                          const float* __restrict__ bp1, const float* __restrict__ bnp,
                          const float* __restrict__ bw1, const float* __restrict__ bnw,
                          const float* __restrict__ bp2, const float* __restrict__ ww1) {
    int t = threadIdx.x;
    if (t < C) {
        float s;
        s = bnq[t] * rsqrtf(bnq[3 * C + t] + EPS);
        g_sq[t] = s; g_tq[t] = (bq[t] - bnq[2 * C + t]) * s + bnq[C + t];
        s = bnk[t] * rsqrtf(bnk[3 * C + t] + EPS);
        g_sk[t] = s; g_tk[t] = (bk[t] - bnk[2 * C + t]) * s + bnk[C + t];
        s = bnp[t] * rsqrtf(bnp[3 * C + t] + EPS);
        g_sp[t] = s; g_tp[t] = (bp1[t] - bnp[2 * C + t]) * s + bnp[C + t];
    }
    if (t < G) {
        float s = bnw[t] * rsqrtf(bnw[3 * G + t] + EPS);
        float bp2w = 0.f;
        for (int c = 0; c < C; c++) bp2w += bp2[c] * ww1[c * G + t];
        g_sw[t] = s;
        g_cw[t] = (bw1[t] + bp2w - bnw[2 * G + t]) * s + bnw[G + t];
    }
}

__global__ void prep_At(const float* __restrict__ wp2, const float* __restrict__ ww1) {
    int kk = blockIdx.x * 16 + (threadIdx.x >> 4);
    int g  = threadIdx.x & 15;
    float s = 0.f;
    #pragma unroll 4
    for (int c = 0; c < C; c++) s = fmaf(wp2[kk * C + c], ww1[c * G + g], s);
    g_A4[((kk >> 2) * G + g) * 4 + (kk & 3)] = s;
}

__global__ void prep_wp2t(const float* __restrict__ wp2) {
    int k = blockIdx.x, c = threadIdx.x;
    g_wp2t[c * C + k] = wp2[k * C + c];
}

__global__ void prep_wi(const float* __restrict__ w, float* __restrict__ dst) {
    int k = blockIdx.x, c = threadIdx.x;
    dst[(k >> 1) * (C * 2) + c * 2 + (k & 1)] = w[k * C + c];
}

// ---------------- K1: fused q/k/v GEMM + Ww1 projections (FFMA2) ----------
// 256 threads = 128 col-threads (2 cols) x 2 row-groups (8 rows each), BM=16
__global__ __launch_bounds__(256, 2) void k1_qkv(
    const float* __restrict__ feat,
    const float* __restrict__ bv, const float* __restrict__ ww1) {
    extern __shared__ float sm[];
    float* feat_s = sm;                 // 16*256
    float* ybuf   = sm + BM * C;        // 16*256
    float* ww1i   = sm + 2 * BM * C;    // [kp][g][2] = 128*32

    int t   = threadIdx.x;
    int r0b = blockIdx.x * BM;

    for (int i = t; i < BM * C / 4; i += 256)
        *(float4*)&feat_s[i * 4] = *(const float4*)&feat[r0b * C + i * 4];
    for (int i = t; i < C * G; i += 256) {
        int k = i >> 4, g = i & 15;
        ww1i[(k >> 1) * 32 + g * 2 + (k & 1)] = ww1[i];
    }
    __syncthreads();

    int ct = t & 127, c0 = ct * 2;
    int rg = t >> 7,  r0 = rg * 8;

    #pragma unroll 1
    for (int pass = 0; pass < 3; pass++) {
        const float* Wi = (pass == 0) ? g_wiq : ((pass == 1) ? g_wik : g_wiv);
        ull acc[8][2];
        #pragma unroll
        for (int r = 0; r < 8; r++) { acc[r][0] = 0ULL; acc[r][1] = 0ULL; }

        #pragma unroll 4
        for (int kq = 0; kq < 128; kq += 2) {
            ulonglong2 wa = *(const ulonglong2*)&Wi[kq * (C * 2) + c0 * 2];
            ulonglong2 wb = *(const ulonglong2*)&Wi[(kq + 1) * (C * 2) + c0 * 2];
            #pragma unroll
            for (int r = 0; r < 8; r++) {
                ulonglong2 f = *(const ulonglong2*)&feat_s[(r0 + r) * C + kq * 2];
                acc[r][0] = fma2(f.x, wa.x, acc[r][0]);
                acc[r][1] = fma2(f.x, wa.y, acc[r][1]);
                acc[r][0] = fma2(f.y, wb.x, acc[r][0]);
                acc[r][1] = fma2(f.y, wb.y, acc[r][1]);
            }
        }

        if (pass == 2) {
            float b0 = bv[c0], b1 = bv[c0 + 1];
            #pragma unroll
            for (int r = 0; r < 8; r++) {
                float2 o;
                o.x = hsum2(acc[r][0]) + b0;
                o.y = hsum2(acc[r][1]) + b1;
                *(float2*)&g_vall[(r0b + r0 + r) * C + c0] = o;
            }
        } else {
            float s0, h0, s1, h1;
            if (pass == 0) { s0 = g_sq[c0]; h0 = g_tq[c0]; s1 = g_sq[c0+1]; h1 = g_tq[c0+1]; }
            else           { s0 = g_sk[c0]; h0 = g_tk[c0]; s1 = g_sk[c0+1]; h1 = g_tk[c0+1]; }
            #pragma unroll
            for (int r = 0; r < 8; r++) {
                float2 y;
                y.x = fmaxf(fmaf(hsum2(acc[r][0]), s0, h0), 0.f);
                y.y = fmaxf(fmaf(hsum2(acc[r][1]), s1, h1), 0.f);
                *(float2*)&ybuf[(r0 + r) * C + c0] = y;
            }
            __syncthreads();
            // projection: 16 rows x 16 g = 256 threads, one (row,g) each
            int g_ = t & 15, rr = t >> 4;
            ull pa = 0ULL;
            #pragma unroll 8
            for (int kq = 0; kq < 128; kq += 2) {
                ulonglong2 y2 = *(const ulonglong2*)&ybuf[rr * C + kq * 2];
                ull w0 = *(const ull*)&ww1i[kq * 32 + g_ * 2];
                ull w1 = *(const ull*)&ww1i[(kq + 1) * 32 + g_ * 2];
                pa = fma2(y2.x, w0, pa);
                pa = fma2(y2.y, w1, pa);
            }
            float* dst = (pass == 0) ? g_qW : g_kW;
            dst[(r0b + rr) * G + g_] = hsum2(pa);
            __syncthreads();   // ybuf reused next pass
        }
    }
}

// ---------------- K2: fused per-point grouped attention -------------------
struct K2S {
    float hid[P * 16 * CP];
    float A4s[4096];
    float buf1[P * 16 * G];
    float buf2[P * 16 * G];
    float pos[P * 16 * 4];
    float wsum[P * G];
    float mask[P * 16];
    int   idx[P * 16];
    float ww2[G * G];
    float bp2s[C];
    float sw[G], cw[G], bw2s[G];
};

__global__ __launch_bounds__(256, 2) void k2_attn(
    const float* __restrict__ coord, const int* __restrict__ knn,
    const float* __restrict__ wp1,   const float* __restrict__ bp2,
    const float* __restrict__ ww2,   const float* __restrict__ bw2,
    float* __restrict__ out) {
    extern __shared__ char smraw[];
    K2S& S = *reinterpret_cast<K2S*>(smraw);
    int t  = threadIdx.x;
    int n0 = blockIdx.x * P;

    for (int i = t; i < 4096; i += 256) S.A4s[i] = g_A4[i];
    S.ww2[t]  = ww2[t];
    S.bp2s[t] = bp2[t];
    if (t < G) { S.sw[t] = g_sw[t]; S.cw[t] = g_cw[t]; S.bw2s[t] = bw2[t]; }

    // phase 1a: gather idx / mask / pos
    if (t < P * 16) {
        int p = t >> 4, n = n0 + p;
        int id  = knn[n * KNN + (t & 15)];
        int ip1 = id + 1;
        float m = (float)((ip1 > 0) - (ip1 < 0));
        int sid = (id > 0) ? id : 0;
        S.idx[t]  = sid;
        S.mask[t] = m;
        #pragma unroll
        for (int d = 0; d < 3; d++)
            S.pos[t * 4 + d] = (coord[sid * 3 + d] - coord[n * 3 + d]) * m;
    }
    __syncthreads();

    // phase 1b: lb = mask*kW[idx] - qW[n]
    for (int o = t; o < P * 16 * G; o += 256) {
        int p = o >> 8, ps = o >> 4, g = o & 15;
        S.buf1[o] = S.mask[ps] * g_kW[S.idx[ps] * G + g] - g_qW[(n0 + p) * G + g];
    }

    // phase 2: hidden = relu(bn(pos @ Wp1 + bp1))
    {
        int c = t;
        float w0 = wp1[c], w1 = wp1[C + c], w2 = wp1[2 * C + c];
        float sc = g_sp[c], sh = g_tp[c];
        #pragma unroll 4
        for (int ps = 0; ps < P * 16; ps++) {
            float px = S.pos[ps * 4 + 0];
            float py = S.pos[ps * 4 + 1];
            float pz = S.pos[ps * 4 + 2];
            float h  = fmaf(px, w0, fmaf(py, w1, pz * w2));
            S.hid[ps * CP + c] = fmaxf(fmaf(h, sc, sh), 0.f);
        }
    }
    __syncthreads();

    // phase 3: u = relu(sw*(hidden@A + lb) + cw); 2x2 tile, FFMA2 over k-pairs
    {
        int pq = t >> 3, gq = t & 7;
        int ps0 = pq * 2, g0 = gq * 2;
        ull a00 = 0ULL, a01 = 0ULL, a10 = 0ULL, a11 = 0ULL;
        const ulonglong2* H0 = (const ulonglong2*)&S.hid[ps0 * CP];
        const ulonglong2* H1 = (const ulonglong2*)&S.hid[(ps0 + 1) * CP];
        const ulonglong2* A4 = (const ulonglong2*)S.A4s;
        #pragma unroll 8
        for (int kb = 0; kb < 64; kb++) {
            ulonglong2 h0 = H0[kb], h1 = H1[kb];
            ulonglong2 b0 = A4[kb * 16 + g0], b1 = A4[kb * 16 + g0 + 1];
            a00 = fma2(h0.x, b0.x, a00); a00 = fma2(h0.y, b0.y, a00);
            a01 = fma2(h0.x, b1.x, a01); a01 = fma2(h0.y, b1.y, a01);
            a10 = fma2(h1.x, b0.x, a10); a10 = fma2(h1.y, b0.y, a10);
            a11 = fma2(h1.x, b1.x, a11); a11 = fma2(h1.y, b1.y, a11);
        }
        float sw0 = S.sw[g0], cw0 = S.cw[g0], sw1 = S.sw[g0 + 1], cw1 = S.cw[g0 + 1];
        int o00 = ps0 * 16 + g0;
        S.buf1[o00]      = fmaxf(fmaf(hsum2(a00) + S.buf1[o00],      sw0, cw0), 0.f);
        S.buf1[o00 + 1]  = fmaxf(fmaf(hsum2(a01) + S.buf1[o00 + 1],  sw1, cw1), 0.f);
        S.buf1[o00 + 16] = fmaxf(fmaf(hsum2(a10) + S.buf1[o00 + 16], sw0, cw0), 0.f);
        S.buf1[o00 + 17] = fmaxf(fmaf(hsum2(a11) + S.buf1[o00 + 17], sw1, cw1), 0.f);
    }
    __syncthreads();

    // phase 3b: logit2 = u @ Ww2 + bw2
    for (int o = t; o < P * 16 * G; o += 256) {
        int ps = o >> 4, g2 = o & 15;
        float acc = S.bw2s[g2];
        const float* u = &S.buf1[ps * 16];
        #pragma unroll
        for (int g = 0; g < 16; g++) acc = fmaf(u[g], S.ww2[g * 16 + g2], acc);
        S.buf2[o] = acc;
    }
    __syncthreads();

    // phase 4a: softmax over s per (p,g); apply mask
    if (t < P * G) {
        int p = t >> 4, g = t & 15;
        float mx = -1e30f;
        #pragma unroll
        for (int s = 0; s < 16; s++) mx = fmaxf(mx, S.buf2[(p * 16 + s) * 16 + g]);
        float e[16], sum = 0.f;
        #pragma unroll
        for (int s = 0; s < 16; s++) {
            e[s] = __expf(S.buf2[(p * 16 + s) * 16 + g] - mx);
            sum += e[s];
        }
        float inv = 1.f / sum, ws = 0.f;
        #pragma unroll
        for (int s = 0; s < 16; s++) {
            float w = e[s] * inv * S.mask[p * 16 + s];
            S.buf2[(p * 16 + s) * 16 + g] = w;
            ws += w;
        }
        S.wsum[t] = ws;
    }
    __syncthreads();

    // phase 4b: hw[p][g][c] = sum_s w[p][s][g]*hid[p][s][c]  (FFMA2 over g-pairs)
    {
        int p = t >> 6, c0 = (t & 63) * 4;
        ull acc2[8][4];
        #pragma unroll
        for (int gp = 0; gp < 8; gp++)
            #pragma unroll
            for (int cc = 0; cc < 4; cc++) acc2[gp][cc] = 0ULL;
        #pragma unroll
        for (int s = 0; s < 16; s++) {
            float4 h = *(const float4*)&S.hid[(p * 16 + s) * CP + c0];
            ull hx = pack2(h.x, h.x), hy = pack2(h.y, h.y);
            ull hz = pack2(h.z, h.z), hw_ = pack2(h.w, h.w);
            const ulonglong2* wv = (const ulonglong2*)&S.buf2[(p * 16 + s) * 16];
            #pragma unroll
            for (int q = 0; q < 4; q++) {
                ulonglong2 w = wv[q];
                acc2[2*q][0]   = fma2(hx,  w.x, acc2[2*q][0]);
                acc2[2*q][1]   = fma2(hy,  w.x, acc2[2*q][1]);
                acc2[2*q][2]   = fma2(hz,  w.x, acc2[2*q][2]);
                acc2[2*q][3]   = fma2(hw_, w.x, acc2[2*q][3]);
                acc2[2*q+1][0] = fma2(hx,  w.y, acc2[2*q+1][0]);
                acc2[2*q+1][1] = fma2(hy,  w.y, acc2[2*q+1][1]);
                acc2[2*q+1][2] = fma2(hz,  w.y, acc2[2*q+1][2]);
                acc2[2*q+1][3] = fma2(hw_, w.y, acc2[2*q+1][3]);
            }
        }
        #pragma unroll
        for (int gp = 0; gp < 8; gp++) {
            float2 e0 = unpk2(acc2[gp][0]), e1 = unpk2(acc2[gp][1]);
            float2 e2 = unpk2(acc2[gp][2]), e3 = unpk2(acc2[gp][3]);
            float4 r0 = make_float4(e0.x, e1.x, e2.x, e3.x);
            float4 r1 = make_float4(e0.y, e1.y, e2.y, e3.y);
            *(float4*)&S.hid[(p * 16 + 2 * gp)     * CP + c0] = r0;
            *(float4*)&S.hid[(p * 16 + 2 * gp + 1) * CP + c0] = r1;
        }
    }
    __syncthreads();

    // phase 5: out = v-gather + hw @ Wp2^T (FFMA2 over k-pairs) + bp2*wsum
    {
        int c = t, g = c >> 4;
        float b = S.bp2s[c];
        float acc0 = b * S.wsum[g],      acc1 = b * S.wsum[16 + g];
        float acc2_ = b * S.wsum[32 + g], acc3 = b * S.wsum[48 + g];

        #pragma unroll
        for (int s = 0; s < 16; s++) {
            int i0 = S.idx[s], i1 = S.idx[16 + s], i2 = S.idx[32 + s], i3 = S.idx[48 + s];
            float v0 = __ldg(&g_vall[i0 * C + c]);
            float v1 = __ldg(&g_vall[i1 * C + c]);
            float v2 = __ldg(&g_vall[i2 * C + c]);
            float v3 = __ldg(&g_vall[i3 * C + c]);
            acc0  = fmaf(S.buf2[(s)      * 16 + g], v0, acc0);
            acc1  = fmaf(S.buf2[(16 + s) * 16 + g], v1, acc1);
            acc2_ = fmaf(S.buf2[(32 + s) * 16 + g], v2, acc2_);
            acc3  = fmaf(S.buf2[(48 + s) * 16 + g], v3, acc3);
        }

        ull m0 = 0ULL, m1 = 0ULL, m2 = 0ULL, m3 = 0ULL;
        const ulonglong2* wpt = (const ulonglong2*)&g_wp2t[c * C];
        const ulonglong2* h0  = (const ulonglong2*)&S.hid[(g)      * CP];
        const ulonglong2* h1  = (const ulonglong2*)&S.hid[(16 + g) * CP];
        const ulonglong2* h2  = (const ulonglong2*)&S.hid[(32 + g) * CP];
        const ulonglong2* h3  = (const ulonglong2*)&S.hid[(48 + g) * CP];
        #pragma unroll 8
        for (int kb = 0; kb < 64; kb++) {
            ulonglong2 wp = wpt[kb];
            ulonglong2 a0 = h0[kb], a1 = h1[kb], a2 = h2[kb], a3 = h3[kb];
            m0 = fma2(wp.x, a0.x, m0); m0 = fma2(wp.y, a0.y, m0);
            m1 = fma2(wp.x, a1.x, m1); m1 = fma2(wp.y, a1.y, m1);
            m2 = fma2(wp.x, a2.x, m2); m2 = fma2(wp.y, a2.y, m2);
            m3 = fma2(wp.x, a3.x, m3); m3 = fma2(wp.y, a3.y, m3);
        }
        out[(n0 + 0) * C + c] = acc0  + hsum2(m0);
        out[(n0 + 1) * C + c] = acc1  + hsum2(m1);
        out[(n0 + 2) * C + c] = acc2_ + hsum2(m2);
        out[(n0 + 3) * C + c] = acc3  + hsum2(m3);
    }
}

// ---------------- launch ----------------------------------------------------
extern "C" void kernel_launch(void* const* d_in, const int* in_sizes, int n_in,
                              void* d_out, int out_size) {
    (void)in_sizes; (void)n_in; (void)out_size;
    const float* feat  = (const float*)d_in[0];
    const float* coord = (const float*)d_in[1];
    const int*   knn   = (const int*)  d_in[2];
    const float* Wq = (const float*)d_in[3];  const float* bq = (const float*)d_in[4];  const float* bnq = (const float*)d_in[5];
    const float* Wk = (const float*)d_in[6];  const float* bk = (const float*)d_in[7];  const float* bnk = (const float*)d_in[8];
    const float* Wv = (const float*)d_in[9];  const float* bv = (const float*)d_in[10];
    const float* Wp1 = (const float*)d_in[11]; const float* bp1 = (const float*)d_in[12]; const float* bnp = (const float*)d_in[13];
    const float* Wp2 = (const float*)d_in[14]; const float* bp2 = (const float*)d_in[15];
    const float* Ww1 = (const float*)d_in[16]; const float* bw1 = (const float*)d_in[17]; const float* bnw = (const float*)d_in[18];
    const float* Ww2 = (const float*)d_in[19]; const float* bw2 = (const float*)d_in[20];
    float* out = (float*)d_out;

    cudaFuncSetAttribute(k1_qkv,  cudaFuncAttributeMaxDynamicSharedMemorySize, 49152);
    cudaFuncSetAttribute(k2_attn, cudaFuncAttributeMaxDynamicSharedMemorySize, (int)sizeof(K2S));

    float *wiq, *wik, *wiv;
    cudaGetSymbolAddress((void**)&wiq, g_wiq);
    cudaGetSymbolAddress((void**)&wik, g_wik);
    cudaGetSymbolAddress((void**)&wiv, g_wiv);

    prep_fold<<<1, 256>>>(bq, bnq, bk, bnk, bp1, bnp, bw1, bnw, bp2, Ww1);
    prep_At<<<16, 256>>>(Wp2, Ww1);
    prep_wp2t<<<C, C>>>(Wp2);
    prep_wi<<<C, C>>>(Wq, wiq);
    prep_wi<<<C, C>>>(Wk, wik);
    prep_wi<<<C, C>>>(Wv, wiv);
    k1_qkv<<<NPTS / BM, 256, 49152>>>(feat, bv, Ww1);
    k2_attn<<<NPTS / P, 256, sizeof(K2S)>>>(coord, knn, Wp1, bp2, Ww2, bw2, out);
}

// round 4
// speedup vs baseline: 1.1494x; 1.1494x over previous
#include <cuda_runtime.h>
#include <math.h>

#define NPTS 20000
#define KNN  16
#define C    256
#define G    16
#define EPS  1e-5f
#define P    4          // points per block in K2
#define BM   32         // feat rows per block in K1
#define CP   260        // padded row stride for hid (float4-stride 65: conflict-free)
#define RP   20         // padded row stride for reduction buffer

// ---------------- scratch (static device memory) ---------------------------
__device__ float g_vall[NPTS * C];
__device__ float g_qW[NPTS * G];
__device__ float g_kW[NPTS * G];
__device__ float g_A4[G * C];          // (Wp2@Ww1), layout [kb][g][4k]
__device__ float g_wp2t[C * C];        // Wp2^T: [c][k]
__device__ float g_sq[C], g_tq[C];
__device__ float g_sk[C], g_tk[C];
__device__ float g_sp[C], g_tp[C];
__device__ float g_sw[G], g_cw[G];

// ---------------- prep kernels ---------------------------------------------
__global__ void prep_fold(const float* __restrict__ bq, const float* __restrict__ bnq,
                          const float* __restrict__ bk, const float* __restrict__ bnk,
                          const float* __restrict__ bp1, const float* __restrict__ bnp,
                          const float* __restrict__ bw1, const float* __restrict__ bnw,
                          const float* __restrict__ bp2, const float* __restrict__ ww1) {
    int t = threadIdx.x;
    if (t < C) {
        float s;
        s = bnq[t] * rsqrtf(bnq[3 * C + t] + EPS);
        g_sq[t] = s; g_tq[t] = (bq[t] - bnq[2 * C + t]) * s + bnq[C + t];
        s = bnk[t] * rsqrtf(bnk[3 * C + t] + EPS);
        g_sk[t] = s; g_tk[t] = (bk[t] - bnk[2 * C + t]) * s + bnk[C + t];
        s = bnp[t] * rsqrtf(bnp[3 * C + t] + EPS);
        g_sp[t] = s; g_tp[t] = (bp1[t] - bnp[2 * C + t]) * s + bnp[C + t];
    }
    if (t < G) {
        float s = bnw[t] * rsqrtf(bnw[3 * G + t] + EPS);
        float bp2w = 0.f;
        for (int c = 0; c < C; c++) bp2w += bp2[c] * ww1[c * G + t];
        g_sw[t] = s;
        g_cw[t] = (bw1[t] + bp2w - bnw[2 * G + t]) * s + bnw[G + t];
    }
}

// A4[kb][g][kk&3] = sum_c Wp2[kk][c] * Ww1[c][g]
__global__ void prep_At(const float* __restrict__ wp2, const float* __restrict__ ww1) {
    int kk = blockIdx.x * 16 + (threadIdx.x >> 4);
    int g  = threadIdx.x & 15;
    float s = 0.f;
    #pragma unroll 4
    for (int c = 0; c < C; c++) s = fmaf(wp2[kk * C + c], ww1[c * G + g], s);
    g_A4[((kk >> 2) * G + g) * 4 + (kk & 3)] = s;
}

__global__ void prep_wp2t(const float* __restrict__ wp2) {
    int k = blockIdx.x, c = threadIdx.x;
    g_wp2t[c * C + k] = wp2[k * C + c];
}

// ---------------- K1: fused q/k/v GEMM + Ww1 projections ------------------
// 256 threads, 3 CTAs/SM. Thread tile: 8 rows x 4 cols.
__global__ __launch_bounds__(256, 3) void k1_qkv(
    const float* __restrict__ feat,
    const float* __restrict__ wq, const float* __restrict__ wk,
    const float* __restrict__ wv, const float* __restrict__ bv,
    const float* __restrict__ ww1) {
    extern __shared__ float sm[];
    float* feat_s = sm;             // 32*256 = 32 KB
    float* ybuf   = sm + BM * C;    // 32*256 = 32 KB

    int t   = threadIdx.x;
    int r0b = blockIdx.x * BM;

    for (int i = t; i < BM * C / 4; i += 256)
        *(float4*)&feat_s[i * 4] = *(const float4*)&feat[r0b * C + i * 4];
    __syncthreads();

    int c0 = (t & 63) * 4;   // output columns c0..c0+3
    int r0 = (t >> 6) * 8;   // output rows r0..r0+7

    #pragma unroll 1
    for (int pass = 0; pass < 3; pass++) {
        const float* W = (pass == 0) ? wq : ((pass == 1) ? wk : wv);
        float acc[8][4];
        #pragma unroll
        for (int r = 0; r < 8; r++)
            #pragma unroll
            for (int c = 0; c < 4; c++) acc[r][c] = 0.f;

        #pragma unroll 2
        for (int k = 0; k < C; k += 4) {
            float4 w0 = *(const float4*)&W[(k + 0) * C + c0];
            float4 w1 = *(const float4*)&W[(k + 1) * C + c0];
            float4 w2 = *(const float4*)&W[(k + 2) * C + c0];
            float4 w3 = *(const float4*)&W[(k + 3) * C + c0];
            #pragma unroll
            for (int r = 0; r < 8; r++) {
                float4 f = *(const float4*)&feat_s[(r0 + r) * C + k];
                acc[r][0] = fmaf(f.x, w0.x, acc[r][0]);
                acc[r][1] = fmaf(f.x, w0.y, acc[r][1]);
                acc[r][2] = fmaf(f.x, w0.z, acc[r][2]);
                acc[r][3] = fmaf(f.x, w0.w, acc[r][3]);
                acc[r][0] = fmaf(f.y, w1.x, acc[r][0]);
                acc[r][1] = fmaf(f.y, w1.y, acc[r][1]);
                acc[r][2] = fmaf(f.y, w1.z, acc[r][2]);
                acc[r][3] = fmaf(f.y, w1.w, acc[r][3]);
                acc[r][0] = fmaf(f.z, w2.x, acc[r][0]);
                acc[r][1] = fmaf(f.z, w2.y, acc[r][1]);
                acc[r][2] = fmaf(f.z, w2.z, acc[r][2]);
                acc[r][3] = fmaf(f.z, w2.w, acc[r][3]);
                acc[r][0] = fmaf(f.w, w3.x, acc[r][0]);
                acc[r][1] = fmaf(f.w, w3.y, acc[r][1]);
                acc[r][2] = fmaf(f.w, w3.z, acc[r][2]);
                acc[r][3] = fmaf(f.w, w3.w, acc[r][3]);
            }
        }

        if (pass == 2) {
            float4 b4 = *(const float4*)&bv[c0];
            #pragma unroll
            for (int r = 0; r < 8; r++) {
                float4 o;
                o.x = acc[r][0] + b4.x; o.y = acc[r][1] + b4.y;
                o.z = acc[r][2] + b4.z; o.w = acc[r][3] + b4.w;
                *(float4*)&g_vall[(r0b + r0 + r) * C + c0] = o;
            }
        } else {
            const float* sA = (pass == 0) ? g_sq : g_sk;
            const float* tA = (pass == 0) ? g_tq : g_tk;
            float4 s4 = *(const float4*)&sA[c0];
            float4 t4 = *(const float4*)&tA[c0];
            #pragma unroll
            for (int r = 0; r < 8; r++) {
                float4 y;
                y.x = fmaxf(fmaf(acc[r][0], s4.x, t4.x), 0.f);
                y.y = fmaxf(fmaf(acc[r][1], s4.y, t4.y), 0.f);
                y.z = fmaxf(fmaf(acc[r][2], s4.z, t4.z), 0.f);
                y.w = fmaxf(fmaf(acc[r][3], s4.w, t4.w), 0.f);
                *(float4*)&ybuf[(r0 + r) * C + c0] = y;
            }
            __syncthreads();
            // projection to 16-dim: thread (rr, g) handles rows rr, rr+16
            int g_ = t & 15, rr = t >> 4;
            float p0 = 0.f, p1 = 0.f;
            #pragma unroll 4
            for (int k = 0; k < C; k += 4) {
                float4 ya = *(const float4*)&ybuf[rr * C + k];
                float4 yb = *(const float4*)&ybuf[(rr + 16) * C + k];
                float q0 = ww1[(k + 0) * G + g_];
                float q1 = ww1[(k + 1) * G + g_];
                float q2 = ww1[(k + 2) * G + g_];
                float q3 = ww1[(k + 3) * G + g_];
                p0 = fmaf(ya.x, q0, p0); p1 = fmaf(yb.x, q0, p1);
                p0 = fmaf(ya.y, q1, p0); p1 = fmaf(yb.y, q1, p1);
                p0 = fmaf(ya.z, q2, p0); p1 = fmaf(yb.z, q2, p1);
                p0 = fmaf(ya.w, q3, p0); p1 = fmaf(yb.w, q3, p1);
            }
            float* dst = (pass == 0) ? g_qW : g_kW;
            dst[(r0b + rr) * G + g_]      = p0;
            dst[(r0b + rr + 16) * G + g_] = p1;
            __syncthreads();   // ybuf reused next pass
        }
    }
}

// ---------------- K2: fused per-point grouped attention -------------------
struct K2S {
    float hid[P * 16 * CP];      // 66560 B; becomes hw in place
    float A4s[4096];             // 16 KB
    float red[4 * 64 * RP];      // 20480 B, k-split partials
    float buf2[P * 16 * G];      // logits -> softmax weights
    float pos[P * 16 * 4];
    float wsum[P * G];
    float mask[P * 16];
    int   idx[P * 16];
    float ww2[G * G];
    float bp2s[C];
    float sw[G], cw[G], bw2s[G];
};

__global__ __launch_bounds__(256, 2) void k2_attn(
    const float* __restrict__ coord, const int* __restrict__ knn,
    const float* __restrict__ wp1,   const float* __restrict__ bp2,
    const float* __restrict__ ww2,   const float* __restrict__ bw2,
    float* __restrict__ out) {
    extern __shared__ char smraw[];
    K2S& S = *reinterpret_cast<K2S*>(smraw);
    int t  = threadIdx.x;
    int n0 = blockIdx.x * P;

    for (int i = t; i < 4096 / 4; i += 256)
        *(float4*)&S.A4s[i * 4] = *(const float4*)&g_A4[i * 4];
    S.ww2[t]  = ww2[t];
    S.bp2s[t] = bp2[t];
    if (t < G) { S.sw[t] = g_sw[t]; S.cw[t] = g_cw[t]; S.bw2s[t] = bw2[t]; }

    // phase 1: gather idx / mask / pos
    if (t < P * 16) {
        int p = t >> 4, n = n0 + p;
        int id  = knn[n * KNN + (t & 15)];
        int ip1 = id + 1;
        float m = (float)((ip1 > 0) - (ip1 < 0));
        int sid = (id > 0) ? id : 0;
        S.idx[t]  = sid;
        S.mask[t] = m;
        #pragma unroll
        for (int d = 0; d < 3; d++)
            S.pos[t * 4 + d] = (coord[sid * 3 + d] - coord[n * 3 + d]) * m;
    }
    __syncthreads();

    // phase 2: hidden = relu(bn(pos @ Wp1 + bp1)); thread t = channel c
    {
        int c = t;
        float w0 = wp1[c], w1 = wp1[C + c], w2 = wp1[2 * C + c];
        float sc = g_sp[c], sh = g_tp[c];
        #pragma unroll 4
        for (int ps = 0; ps < P * 16; ps++) {
            float px = S.pos[ps * 4 + 0];
            float py = S.pos[ps * 4 + 1];
            float pz = S.pos[ps * 4 + 2];
            float h  = fmaf(px, w0, fmaf(py, w1, pz * w2));
            S.hid[ps * CP + c] = fmaxf(fmaf(h, sc, sh), 0.f);
        }
    }
    __syncthreads();

    // phase 3a: k-split partial of hidden @ A  (warp-uniform k-quarter)
    {
        int kq = t >> 6, row = t & 63;
        const float4* hp = (const float4*)&S.hid[row * CP + kq * 64];
        float acc[16];
        #pragma unroll
        for (int g = 0; g < 16; g++) acc[g] = 0.f;
        #pragma unroll 4
        for (int i = 0; i < 16; i++) {
            float4 h = hp[i];
            const float4* a = (const float4*)&S.A4s[(kq * 16 + i) * 64];
            #pragma unroll
            for (int g = 0; g < 16; g++) {
                float4 av = a[g];
                acc[g] = fmaf(h.x, av.x, acc[g]);
                acc[g] = fmaf(h.y, av.y, acc[g]);
                acc[g] = fmaf(h.z, av.z, acc[g]);
                acc[g] = fmaf(h.w, av.w, acc[g]);
            }
        }
        float* rd = &S.red[(kq * 64 + row) * RP];
        #pragma unroll
        for (int q = 0; q < 4; q++)
            *(float4*)&rd[q * 4] = make_float4(acc[q*4], acc[q*4+1], acc[q*4+2], acc[q*4+3]);
    }
    __syncthreads();

    // phase 3b (64 threads): reduce partials + lb + relu/sw/cw + @Ww2 -> buf2
    if (t < 64) {
        int r = t, p = r >> 4;
        float m = S.mask[r];
        int  id = S.idx[r];
        const float4* kw = (const float4*)&g_kW[id * G];
        const float4* qw = (const float4*)&g_qW[(n0 + p) * G];
        float u[16];
        #pragma unroll
        for (int q = 0; q < 4; q++) {
            float4 s0 = *(const float4*)&S.red[(0 * 64 + r) * RP + q * 4];
            float4 s1 = *(const float4*)&S.red[(1 * 64 + r) * RP + q * 4];
            float4 s2 = *(const float4*)&S.red[(2 * 64 + r) * RP + q * 4];
            float4 s3 = *(const float4*)&S.red[(3 * 64 + r) * RP + q * 4];
            float4 kv = kw[q], qv = qw[q];
            float4 lb;
            lb.x = fmaf(m, kv.x, -qv.x); lb.y = fmaf(m, kv.y, -qv.y);
            lb.z = fmaf(m, kv.z, -qv.z); lb.w = fmaf(m, kv.w, -qv.w);
            u[q*4+0] = fmaxf(fmaf(s0.x + s1.x + s2.x + s3.x + lb.x, S.sw[q*4+0], S.cw[q*4+0]), 0.f);
            u[q*4+1] = fmaxf(fmaf(s0.y + s1.y + s2.y + s3.y + lb.y, S.sw[q*4+1], S.cw[q*4+1]), 0.f);
            u[q*4+2] = fmaxf(fmaf(s0.z + s1.z + s2.z + s3.z + lb.z, S.sw[q*4+2], S.cw[q*4+2]), 0.f);
            u[q*4+3] = fmaxf(fmaf(s0.w + s1.w + s2.w + s3.w + lb.w, S.sw[q*4+3], S.cw[q*4+3]), 0.f);
        }
        #pragma unroll
        for (int g2 = 0; g2 < 16; g2++) {
            float acc = S.bw2s[g2];
            #pragma unroll
            for (int g = 0; g < 16; g++) acc = fmaf(u[g], S.ww2[g * 16 + g2], acc);
            S.buf2[r * 16 + g2] = acc;
        }
    }
    __syncthreads();

    // phase 4a: softmax over s per (p,g); apply mask
    if (t < P * G) {
        int p = t >> 4, g = t & 15;
        float mx = -1e30f;
        #pragma unroll
        for (int s = 0; s < 16; s++) mx = fmaxf(mx, S.buf2[(p * 16 + s) * 16 + g]);
        float e[16], sum = 0.f;
        #pragma unroll
        for (int s = 0; s < 16; s++) {
            e[s] = __expf(S.buf2[(p * 16 + s) * 16 + g] - mx);
            sum += e[s];
        }
        float inv = 1.f / sum, ws = 0.f;
        #pragma unroll
        for (int s = 0; s < 16; s++) {
            float w = e[s] * inv * S.mask[p * 16 + s];
            S.buf2[(p * 16 + s) * 16 + g] = w;
            ws += w;
        }
        S.wsum[t] = ws;
    }
    __syncthreads();

    // phase 4b: hw[p][g][c] = sum_s w[p][s][g]*hid[p][s][c]  (in place)
    {
        int p = t >> 6, c0 = (t & 63) * 4;
        float4 acc[16];
        #pragma unroll
        for (int g = 0; g < 16; g++) acc[g] = make_float4(0.f, 0.f, 0.f, 0.f);
        const float4* wv4 = (const float4*)S.buf2;
        #pragma unroll
        for (int s = 0; s < 16; s++) {
            float4 h = *(const float4*)&S.hid[(p * 16 + s) * CP + c0];
            #pragma unroll
            for (int q = 0; q < 4; q++) {
                float4 w = wv4[(p * 16 + s) * 4 + q];
                acc[q*4+0].x = fmaf(w.x, h.x, acc[q*4+0].x); acc[q*4+0].y = fmaf(w.x, h.y, acc[q*4+0].y);
                acc[q*4+0].z = fmaf(w.x, h.z, acc[q*4+0].z); acc[q*4+0].w = fmaf(w.x, h.w, acc[q*4+0].w);
                acc[q*4+1].x = fmaf(w.y, h.x, acc[q*4+1].x); acc[q*4+1].y = fmaf(w.y, h.y, acc[q*4+1].y);
                acc[q*4+1].z = fmaf(w.y, h.z, acc[q*4+1].z); acc[q*4+1].w = fmaf(w.y, h.w, acc[q*4+1].w);
                acc[q*4+2].x = fmaf(w.z, h.x, acc[q*4+2].x); acc[q*4+2].y = fmaf(w.z, h.y, acc[q*4+2].y);
                acc[q*4+2].z = fmaf(w.z, h.z, acc[q*4+2].z); acc[q*4+2].w = fmaf(w.z, h.w, acc[q*4+2].w);
                acc[q*4+3].x = fmaf(w.w, h.x, acc[q*4+3].x); acc[q*4+3].y = fmaf(w.w, h.y, acc[q*4+3].y);
                acc[q*4+3].z = fmaf(w.w, h.z, acc[q*4+3].z); acc[q*4+3].w = fmaf(w.w, h.w, acc[q*4+3].w);
            }
        }
        #pragma unroll
        for (int g = 0; g < 16; g++)
            *(float4*)&S.hid[(p * 16 + g) * CP + c0] = acc[g];
    }
    __syncthreads();

    // phase 5: out = v-gather + hw @ Wp2^T + bp2*wsum
    {
        int c = t, g = c >> 4;
        float b = S.bp2s[c];
        float acc0 = b * S.wsum[g],       acc1 = b * S.wsum[16 + g];
        float acc2 = b * S.wsum[32 + g],  acc3 = b * S.wsum[48 + g];

        #pragma unroll
        for (int s = 0; s < 16; s++) {
            int i0 = S.idx[s], i1 = S.idx[16 + s], i2 = S.idx[32 + s], i3 = S.idx[48 + s];
            float v0 = __ldg(&g_vall[i0 * C + c]);
            float v1 = __ldg(&g_vall[i1 * C + c]);
            float v2 = __ldg(&g_vall[i2 * C + c]);
            float v3 = __ldg(&g_vall[i3 * C + c]);
            acc0 = fmaf(S.buf2[(s)      * 16 + g], v0, acc0);
            acc1 = fmaf(S.buf2[(16 + s) * 16 + g], v1, acc1);
            acc2 = fmaf(S.buf2[(32 + s) * 16 + g], v2, acc2);
            acc3 = fmaf(S.buf2[(48 + s) * 16 + g], v3, acc3);
        }

        const float4* wpt = (const float4*)&g_wp2t[c * C];
        const float4* h0  = (const float4*)&S.hid[(g)      * CP];
        const float4* h1  = (const float4*)&S.hid[(16 + g) * CP];
        const float4* h2  = (const float4*)&S.hid[(32 + g) * CP];
        const float4* h3  = (const float4*)&S.hid[(48 + g) * CP];
        #pragma unroll 4
        for (int kb = 0; kb < 64; kb++) {
            float4 wp = wpt[kb];
            float4 a0 = h0[kb], a1 = h1[kb], a2 = h2[kb], a3 = h3[kb];
            acc0 = fmaf(wp.x, a0.x, acc0); acc0 = fmaf(wp.y, a0.y, acc0);
            acc0 = fmaf(wp.z, a0.z, acc0); acc0 = fmaf(wp.w, a0.w, acc0);
            acc1 = fmaf(wp.x, a1.x, acc1); acc1 = fmaf(wp.y, a1.y, acc1);
            acc1 = fmaf(wp.z, a1.z, acc1); acc1 = fmaf(wp.w, a1.w, acc1);
            acc2 = fmaf(wp.x, a2.x, acc2); acc2 = fmaf(wp.y, a2.y, acc2);
            acc2 = fmaf(wp.z, a2.z, acc2); acc2 = fmaf(wp.w, a2.w, acc2);
            acc3 = fmaf(wp.x, a3.x, acc3); acc3 = fmaf(wp.y, a3.y, acc3);
            acc3 = fmaf(wp.z, a3.z, acc3); acc3 = fmaf(wp.w, a3.w, acc3);
        }
        out[(n0 + 0) * C + c] = acc0;
        out[(n0 + 1) * C + c] = acc1;
        out[(n0 + 2) * C + c] = acc2;
        out[(n0 + 3) * C + c] = acc3;
    }
}

// ---------------- launch ----------------------------------------------------
extern "C" void kernel_launch(void* const* d_in, const int* in_sizes, int n_in,
                              void* d_out, int out_size) {
    (void)in_sizes; (void)n_in; (void)out_size;
    const float* feat  = (const float*)d_in[0];
    const float* coord = (const float*)d_in[1];
    const int*   knn   = (const int*)  d_in[2];
    const float* Wq = (const float*)d_in[3];  const float* bq = (const float*)d_in[4];  const float* bnq = (const float*)d_in[5];
    const float* Wk = (const float*)d_in[6];  const float* bk = (const float*)d_in[7];  const float* bnk = (const float*)d_in[8];
    const float* Wv = (const float*)d_in[9];  const float* bv = (const float*)d_in[10];
    const float* Wp1 = (const float*)d_in[11]; const float* bp1 = (const float*)d_in[12]; const float* bnp = (const float*)d_in[13];
    const float* Wp2 = (const float*)d_in[14]; const float* bp2 = (const float*)d_in[15];
    const float* Ww1 = (const float*)d_in[16]; const float* bw1 = (const float*)d_in[17]; const float* bnw = (const float*)d_in[18];
    const float* Ww2 = (const float*)d_in[19]; const float* bw2 = (const float*)d_in[20];
    float* out = (float*)d_out;

    cudaFuncSetAttribute(k1_qkv,  cudaFuncAttributeMaxDynamicSharedMemorySize, 2 * BM * C * 4);
    cudaFuncSetAttribute(k2_attn, cudaFuncAttributeMaxDynamicSharedMemorySize, (int)sizeof(K2S));

    prep_fold<<<1, 256>>>(bq, bnq, bk, bnk, bp1, bnp, bw1, bnw, bp2, Ww1);
    prep_At<<<16, 256>>>(Wp2, Ww1);
    prep_wp2t<<<C, C>>>(Wp2);
    k1_qkv<<<NPTS / BM, 256, 2 * BM * C * 4>>>(feat, Wq, Wk, Wv, bv, Ww1);
    k2_attn<<<NPTS / P, 256, sizeof(K2S)>>>(coord, knn, Wp1, bp2, Ww2, bw2, out);
}

// round 5
// speedup vs baseline: 1.2613x; 1.0973x over previous
#include <cuda_runtime.h>
#include <math.h>

#define NPTS 20000
#define KNN  16
#define C    256
#define G    16
#define EPS  1e-5f
#define P    4          // points per block in K2
#define BM   32         // feat rows per block in K1
#define CP   260        // padded row stride for hid
#define RP   20         // padded row stride for reduction buffer
#define FS   260        // k1 feat_s stride (A-frag conflict-free)
#define WS   264        // k1 wbuf stride (B-frag conflict-free)

// ---------------- scratch (static device memory) ---------------------------
__device__ float g_vall[NPTS * C];
__device__ float g_qW[NPTS * G];
__device__ float g_kW[NPTS * G];
__device__ float g_A4[G * C];          // (Wp2@Ww1), layout [kb][g][4k]
__device__ float g_wp2t[C * C];        // Wp2^T: [c][k]
__device__ float g_sq[C], g_tq[C];
__device__ float g_sk[C], g_tk[C];
__device__ float g_sp[C], g_tp[C];
__device__ float g_sw[G], g_cw[G];

// ---------------- tf32 helpers ---------------------------------------------
__device__ __forceinline__ unsigned f2tf(float x) {
    unsigned r;
    asm("cvt.rna.tf32.f32 %0, %1;" : "=r"(r) : "f"(x));
    return r;
}

// ---------------- prep kernels ---------------------------------------------
__global__ void prep_fold(const float* __restrict__ bq, const float* __restrict__ bnq,
                          const float* __restrict__ bk, const float* __restrict__ bnk,
                          const float* __restrict__ bp1, const float* __restrict__ bnp,
                          const float* __restrict__ bw1, const float* __restrict__ bnw,
                          const float* __restrict__ bp2, const float* __restrict__ ww1) {
    int t = threadIdx.x;
    if (t < C) {
        float s;
        s = bnq[t] * rsqrtf(bnq[3 * C + t] + EPS);
        g_sq[t] = s; g_tq[t] = (bq[t] - bnq[2 * C + t]) * s + bnq[C + t];
        s = bnk[t] * rsqrtf(bnk[3 * C + t] + EPS);
        g_sk[t] = s; g_tk[t] = (bk[t] - bnk[2 * C + t]) * s + bnk[C + t];
        s = bnp[t] * rsqrtf(bnp[3 * C + t] + EPS);
        g_sp[t] = s; g_tp[t] = (bp1[t] - bnp[2 * C + t]) * s + bnp[C + t];
    }
    if (t < G) {
        float s = bnw[t] * rsqrtf(bnw[3 * G + t] + EPS);
        float bp2w = 0.f;
        for (int c = 0; c < C; c++) bp2w += bp2[c] * ww1[c * G + t];
        g_sw[t] = s;
        g_cw[t] = (bw1[t] + bp2w - bnw[2 * G + t]) * s + bnw[G + t];
    }
}

__global__ void prep_At(const float* __restrict__ wp2, const float* __restrict__ ww1) {
    int kk = blockIdx.x * 16 + (threadIdx.x >> 4);
    int g  = threadIdx.x & 15;
    float s = 0.f;
    #pragma unroll 4
    for (int c = 0; c < C; c++) s = fmaf(wp2[kk * C + c], ww1[c * G + g], s);
    g_A4[((kk >> 2) * G + g) * 4 + (kk & 3)] = s;
}

__global__ void prep_wp2t(const float* __restrict__ wp2) {
    int k = blockIdx.x, c = threadIdx.x;
    g_wp2t[c * C + k] = wp2[k * C + c];
}

// ---------------- K1: fused q/k/v GEMM via TF32 mma.sync -------------------
// 8 warps; warp tile m16 x n64 (2 x 4 warp grid over 32 x 256 block tile).
__global__ __launch_bounds__(256, 2) void k1_qkv(
    const float* __restrict__ feat,
    const float* __restrict__ wq, const float* __restrict__ wk,
    const float* __restrict__ wv, const float* __restrict__ bv,
    const float* __restrict__ ww1) {
    extern __shared__ float sm[];
    float* feat_s = sm;                       // 32*FS
    float* wbuf   = sm + BM * FS;             // 32*WS
    float* ybuf   = sm + BM * FS + 32 * WS;   // 32*256
    unsigned* featu = (unsigned*)feat_s;
    unsigned* wbufu = (unsigned*)wbuf;

    int t   = threadIdx.x;
    int r0b = blockIdx.x * BM;
    int warp = t >> 5, lane = t & 31;
    int gid = lane >> 2, tig = lane & 3;
    int m0 = (warp & 1) * 16;
    int n0 = (warp >> 1) * 64;

    // stage feat tile, tf32-converted
    for (int i = t; i < BM * C / 4; i += 256) {
        int r = i >> 6, c4 = (i & 63) * 4;
        float4 f = *(const float4*)&feat[(r0b + r) * C + c4];
        featu[r * FS + c4 + 0] = f2tf(f.x);
        featu[r * FS + c4 + 1] = f2tf(f.y);
        featu[r * FS + c4 + 2] = f2tf(f.z);
        featu[r * FS + c4 + 3] = f2tf(f.w);
    }

    #pragma unroll 1
    for (int pass = 0; pass < 3; pass++) {
        const float* W = (pass == 0) ? wq : ((pass == 1) ? wk : wv);
        float4 acc[8];
        #pragma unroll
        for (int nt = 0; nt < 8; nt++) acc[nt] = make_float4(0.f, 0.f, 0.f, 0.f);

        #pragma unroll 1
        for (int kc = 0; kc < C; kc += 32) {
            __syncthreads();   // protect wbuf (and feat_s on first iter / ybuf across passes)
            for (int i = t; i < 32 * C / 4; i += 256) {
                int r = i >> 6, c4 = (i & 63) * 4;
                float4 f = *(const float4*)&W[(kc + r) * C + c4];
                wbufu[r * WS + c4 + 0] = f2tf(f.x);
                wbufu[r * WS + c4 + 1] = f2tf(f.y);
                wbufu[r * WS + c4 + 2] = f2tf(f.z);
                wbufu[r * WS + c4 + 3] = f2tf(f.w);
            }
            __syncthreads();
            #pragma unroll
            for (int kk = 0; kk < 32; kk += 8) {
                unsigned a0 = featu[(m0 + gid)     * FS + kc + kk + tig];
                unsigned a1 = featu[(m0 + gid + 8) * FS + kc + kk + tig];
                unsigned a2 = featu[(m0 + gid)     * FS + kc + kk + tig + 4];
                unsigned a3 = featu[(m0 + gid + 8) * FS + kc + kk + tig + 4];
                #pragma unroll
                for (int nt = 0; nt < 8; nt++) {
                    unsigned b0 = wbufu[(kk + tig)     * WS + n0 + nt * 8 + gid];
                    unsigned b1 = wbufu[(kk + tig + 4) * WS + n0 + nt * 8 + gid];
                    asm("mma.sync.aligned.m16n8k8.row.col.f32.tf32.tf32.f32 "
                        "{%0,%1,%2,%3},{%4,%5,%6,%7},{%8,%9},{%0,%1,%2,%3};"
                        : "+f"(acc[nt].x), "+f"(acc[nt].y), "+f"(acc[nt].z), "+f"(acc[nt].w)
                        : "r"(a0), "r"(a1), "r"(a2), "r"(a3), "r"(b0), "r"(b1));
                }
            }
        }

        if (pass == 2) {
            #pragma unroll
            for (int nt = 0; nt < 8; nt++) {
                int col = n0 + nt * 8 + tig * 2;
                float2 b2 = *(const float2*)&bv[col];
                *(float2*)&g_vall[(r0b + m0 + gid)     * C + col] =
                    make_float2(acc[nt].x + b2.x, acc[nt].y + b2.y);
                *(float2*)&g_vall[(r0b + m0 + gid + 8) * C + col] =
                    make_float2(acc[nt].z + b2.x, acc[nt].w + b2.y);
            }
        } else {
            const float* sA = (pass == 0) ? g_sq : g_sk;
            const float* tA = (pass == 0) ? g_tq : g_tk;
            #pragma unroll
            for (int nt = 0; nt < 8; nt++) {
                int col = n0 + nt * 8 + tig * 2;
                float2 s2 = *(const float2*)&sA[col];
                float2 t2 = *(const float2*)&tA[col];
                *(float2*)&ybuf[(m0 + gid) * C + col] = make_float2(
                    fmaxf(fmaf(acc[nt].x, s2.x, t2.x), 0.f),
                    fmaxf(fmaf(acc[nt].y, s2.y, t2.y), 0.f));
                *(float2*)&ybuf[(m0 + gid + 8) * C + col] = make_float2(
                    fmaxf(fmaf(acc[nt].z, s2.x, t2.x), 0.f),
                    fmaxf(fmaf(acc[nt].w, s2.y, t2.y), 0.f));
            }
            __syncthreads();
            // projection to 16-dim: thread (rr, g) handles rows rr, rr+16
            int g_ = t & 15, rr = t >> 4;
            float p0 = 0.f, p1 = 0.f;
            #pragma unroll 4
            for (int k = 0; k < C; k += 4) {
                float4 ya = *(const float4*)&ybuf[rr * C + k];
                float4 yb = *(const float4*)&ybuf[(rr + 16) * C + k];
                float q0 = ww1[(k + 0) * G + g_];
                float q1 = ww1[(k + 1) * G + g_];
                float q2 = ww1[(k + 2) * G + g_];
                float q3 = ww1[(k + 3) * G + g_];
                p0 = fmaf(ya.x, q0, p0); p1 = fmaf(yb.x, q0, p1);
                p0 = fmaf(ya.y, q1, p0); p1 = fmaf(yb.y, q1, p1);
                p0 = fmaf(ya.z, q2, p0); p1 = fmaf(yb.z, q2, p1);
                p0 = fmaf(ya.w, q3, p0); p1 = fmaf(yb.w, q3, p1);
            }
            float* dst = (pass == 0) ? g_qW : g_kW;
            dst[(r0b + rr) * G + g_]      = p0;
            dst[(r0b + rr + 16) * G + g_] = p1;
            // no trailing sync needed: next pass's first chunk-sync protects ybuf
        }
    }
}

// ---------------- K2: fused per-point grouped attention -------------------
struct K2S {
    float hid[P * 16 * CP];      // becomes hw in place
    float A4s[4096];
    float red[4 * 64 * RP];
    float buf2[P * 16 * G];
    float pos[P * 16 * 4];
    float wsum[P * G];
    float mask[P * 16];
    int   idx[P * 16];
    float ww2[G * G];
    float bp2s[C];
    float sw[G], cw[G], bw2s[G];
};

__global__ __launch_bounds__(256, 2) void k2_attn(
    const float* __restrict__ coord, const int* __restrict__ knn,
    const float* __restrict__ wp1,   const float* __restrict__ bp2,
    const float* __restrict__ ww2,   const float* __restrict__ bw2,
    float* __restrict__ out) {
    extern __shared__ char smraw[];
    K2S& S = *reinterpret_cast<K2S*>(smraw);
    int t  = threadIdx.x;
    int n0 = blockIdx.x * P;

    for (int i = t; i < 4096 / 4; i += 256)
        *(float4*)&S.A4s[i * 4] = *(const float4*)&g_A4[i * 4];
    S.ww2[t]  = ww2[t];
    S.bp2s[t] = bp2[t];
    if (t < G) { S.sw[t] = g_sw[t]; S.cw[t] = g_cw[t]; S.bw2s[t] = bw2[t]; }

    // phase 1: gather idx / mask / pos
    if (t < P * 16) {
        int p = t >> 4, n = n0 + p;
        int id  = knn[n * KNN + (t & 15)];
        int ip1 = id + 1;
        float m = (float)((ip1 > 0) - (ip1 < 0));
        int sid = (id > 0) ? id : 0;
        S.idx[t]  = sid;
        S.mask[t] = m;
        #pragma unroll
        for (int d = 0; d < 3; d++)
            S.pos[t * 4 + d] = (coord[sid * 3 + d] - coord[n * 3 + d]) * m;
    }
    __syncthreads();

    // phase 2: hidden = relu(bn(pos @ Wp1 + bp1))
    {
        int c = t;
        float w0 = wp1[c], w1 = wp1[C + c], w2 = wp1[2 * C + c];
        float sc = g_sp[c], sh = g_tp[c];
        #pragma unroll 4
        for (int ps = 0; ps < P * 16; ps++) {
            float px = S.pos[ps * 4 + 0];
            float py = S.pos[ps * 4 + 1];
            float pz = S.pos[ps * 4 + 2];
            float h  = fmaf(px, w0, fmaf(py, w1, pz * w2));
            S.hid[ps * CP + c] = fmaxf(fmaf(h, sc, sh), 0.f);
        }
    }
    __syncthreads();

    // phase 3a: k-split partial of hidden @ A
    {
        int kq = t >> 6, row = t & 63;
        const float4* hp = (const float4*)&S.hid[row * CP + kq * 64];
        float acc[16];
        #pragma unroll
        for (int g = 0; g < 16; g++) acc[g] = 0.f;
        #pragma unroll 4
        for (int i = 0; i < 16; i++) {
            float4 h = hp[i];
            const float4* a = (const float4*)&S.A4s[(kq * 16 + i) * 64];
            #pragma unroll
            for (int g = 0; g < 16; g++) {
                float4 av = a[g];
                acc[g] = fmaf(h.x, av.x, acc[g]);
                acc[g] = fmaf(h.y, av.y, acc[g]);
                acc[g] = fmaf(h.z, av.z, acc[g]);
                acc[g] = fmaf(h.w, av.w, acc[g]);
            }
        }
        float* rd = &S.red[(kq * 64 + row) * RP];
        #pragma unroll
        for (int q = 0; q < 4; q++)
            *(float4*)&rd[q * 4] = make_float4(acc[q*4], acc[q*4+1], acc[q*4+2], acc[q*4+3]);
    }
    __syncthreads();

    // phase 3b (64 threads): reduce + lb + relu/sw/cw + @Ww2 -> buf2
    if (t < 64) {
        int r = t, p = r >> 4;
        float m = S.mask[r];
        int  id = S.idx[r];
        const float4* kw = (const float4*)&g_kW[id * G];
        const float4* qw = (const float4*)&g_qW[(n0 + p) * G];
        float u[16];
        #pragma unroll
        for (int q = 0; q < 4; q++) {
            float4 s0 = *(const float4*)&S.red[(0 * 64 + r) * RP + q * 4];
            float4 s1 = *(const float4*)&S.red[(1 * 64 + r) * RP + q * 4];
            float4 s2 = *(const float4*)&S.red[(2 * 64 + r) * RP + q * 4];
            float4 s3 = *(const float4*)&S.red[(3 * 64 + r) * RP + q * 4];
            float4 kv = kw[q], qv = qw[q];
            float4 lb;
            lb.x = fmaf(m, kv.x, -qv.x); lb.y = fmaf(m, kv.y, -qv.y);
            lb.z = fmaf(m, kv.z, -qv.z); lb.w = fmaf(m, kv.w, -qv.w);
            u[q*4+0] = fmaxf(fmaf(s0.x + s1.x + s2.x + s3.x + lb.x, S.sw[q*4+0], S.cw[q*4+0]), 0.f);
            u[q*4+1] = fmaxf(fmaf(s0.y + s1.y + s2.y + s3.y + lb.y, S.sw[q*4+1], S.cw[q*4+1]), 0.f);
            u[q*4+2] = fmaxf(fmaf(s0.z + s1.z + s2.z + s3.z + lb.z, S.sw[q*4+2], S.cw[q*4+2]), 0.f);
            u[q*4+3] = fmaxf(fmaf(s0.w + s1.w + s2.w + s3.w + lb.w, S.sw[q*4+3], S.cw[q*4+3]), 0.f);
        }
        #pragma unroll
        for (int g2 = 0; g2 < 16; g2++) {
            float acc = S.bw2s[g2];
            #pragma unroll
            for (int g = 0; g < 16; g++) acc = fmaf(u[g], S.ww2[g * 16 + g2], acc);
            S.buf2[r * 16 + g2] = acc;
        }
    }
    __syncthreads();

    // phase 4a: softmax over s per (p,g)
    if (t < P * G) {
        int p = t >> 4, g = t & 15;
        float mx = -1e30f;
        #pragma unroll
        for (int s = 0; s < 16; s++) mx = fmaxf(mx, S.buf2[(p * 16 + s) * 16 + g]);
        float e[16], sum = 0.f;
        #pragma unroll
        for (int s = 0; s < 16; s++) {
            e[s] = __expf(S.buf2[(p * 16 + s) * 16 + g] - mx);
            sum += e[s];
        }
        float inv = 1.f / sum, ws = 0.f;
        #pragma unroll
        for (int s = 0; s < 16; s++) {
            float w = e[s] * inv * S.mask[p * 16 + s];
            S.buf2[(p * 16 + s) * 16 + g] = w;
            ws += w;
        }
        S.wsum[t] = ws;
    }
    __syncthreads();

    // phase 4b: hw[p][g][c] = sum_s w[p][s][g]*hid[p][s][c]  (in place)
    {
        int p = t >> 6, c0 = (t & 63) * 4;
        float4 acc[16];
        #pragma unroll
        for (int g = 0; g < 16; g++) acc[g] = make_float4(0.f, 0.f, 0.f, 0.f);
        const float4* wv4 = (const float4*)S.buf2;
        #pragma unroll
        for (int s = 0; s < 16; s++) {
            float4 h = *(const float4*)&S.hid[(p * 16 + s) * CP + c0];
            #pragma unroll
            for (int q = 0; q < 4; q++) {
                float4 w = wv4[(p * 16 + s) * 4 + q];
                acc[q*4+0].x = fmaf(w.x, h.x, acc[q*4+0].x); acc[q*4+0].y = fmaf(w.x, h.y, acc[q*4+0].y);
                acc[q*4+0].z = fmaf(w.x, h.z, acc[q*4+0].z); acc[q*4+0].w = fmaf(w.x, h.w, acc[q*4+0].w);
                acc[q*4+1].x = fmaf(w.y, h.x, acc[q*4+1].x); acc[q*4+1].y = fmaf(w.y, h.y, acc[q*4+1].y);
                acc[q*4+1].z = fmaf(w.y, h.z, acc[q*4+1].z); acc[q*4+1].w = fmaf(w.y, h.w, acc[q*4+1].w);
                acc[q*4+2].x = fmaf(w.z, h.x, acc[q*4+2].x); acc[q*4+2].y = fmaf(w.z, h.y, acc[q*4+2].y);
                acc[q*4+2].z = fmaf(w.z, h.z, acc[q*4+2].z); acc[q*4+2].w = fmaf(w.z, h.w, acc[q*4+2].w);
                acc[q*4+3].x = fmaf(w.w, h.x, acc[q*4+3].x); acc[q*4+3].y = fmaf(w.w, h.y, acc[q*4+3].y);
                acc[q*4+3].z = fmaf(w.w, h.z, acc[q*4+3].z); acc[q*4+3].w = fmaf(w.w, h.w, acc[q*4+3].w);
            }
        }
        #pragma unroll
        for (int g = 0; g < 16; g++)
            *(float4*)&S.hid[(p * 16 + g) * CP + c0] = acc[g];
    }
    __syncthreads();

    // phase 5: out = v-gather + hw @ Wp2^T + bp2*wsum
    {
        int c = t, g = c >> 4;
        float b = S.bp2s[c];
        float acc0 = b * S.wsum[g],       acc1 = b * S.wsum[16 + g];
        float acc2 = b * S.wsum[32 + g],  acc3 = b * S.wsum[48 + g];

        #pragma unroll
        for (int s = 0; s < 16; s++) {
            int i0 = S.idx[s], i1 = S.idx[16 + s], i2 = S.idx[32 + s], i3 = S.idx[48 + s];
            float v0 = __ldg(&g_vall[i0 * C + c]);
            float v1 = __ldg(&g_vall[i1 * C + c]);
            float v2 = __ldg(&g_vall[i2 * C + c]);
            float v3 = __ldg(&g_vall[i3 * C + c]);
            acc0 = fmaf(S.buf2[(s)      * 16 + g], v0, acc0);
            acc1 = fmaf(S.buf2[(16 + s) * 16 + g], v1, acc1);
            acc2 = fmaf(S.buf2[(32 + s) * 16 + g], v2, acc2);
            acc3 = fmaf(S.buf2[(48 + s) * 16 + g], v3, acc3);
        }

        const float4* wpt = (const float4*)&g_wp2t[c * C];
        const float4* h0  = (const float4*)&S.hid[(g)      * CP];
        const float4* h1  = (const float4*)&S.hid[(16 + g) * CP];
        const float4* h2  = (const float4*)&S.hid[(32 + g) * CP];
        const float4* h3  = (const float4*)&S.hid[(48 + g) * CP];
        #pragma unroll 4
        for (int kb = 0; kb < 64; kb++) {
            float4 wp = wpt[kb];
            float4 a0 = h0[kb], a1 = h1[kb], a2 = h2[kb], a3 = h3[kb];
            acc0 = fmaf(wp.x, a0.x, acc0); acc0 = fmaf(wp.y, a0.y, acc0);
            acc0 = fmaf(wp.z, a0.z, acc0); acc0 = fmaf(wp.w, a0.w, acc0);
            acc1 = fmaf(wp.x, a1.x, acc1); acc1 = fmaf(wp.y, a1.y, acc1);
            acc1 = fmaf(wp.z, a1.z, acc1); acc1 = fmaf(wp.w, a1.w, acc1);
            acc2 = fmaf(wp.x, a2.x, acc2); acc2 = fmaf(wp.y, a2.y, acc2);
            acc2 = fmaf(wp.z, a2.z, acc2); acc2 = fmaf(wp.w, a2.w, acc2);
            acc3 = fmaf(wp.x, a3.x, acc3); acc3 = fmaf(wp.y, a3.y, acc3);
            acc3 = fmaf(wp.z, a3.z, acc3); acc3 = fmaf(wp.w, a3.w, acc3);
        }
        out[(n0 + 0) * C + c] = acc0;
        out[(n0 + 1) * C + c] = acc1;
        out[(n0 + 2) * C + c] = acc2;
        out[(n0 + 3) * C + c] = acc3;
    }
}

// ---------------- launch ----------------------------------------------------
extern "C" void kernel_launch(void* const* d_in, const int* in_sizes, int n_in,
                              void* d_out, int out_size) {
    (void)in_sizes; (void)n_in; (void)out_size;
    const float* feat  = (const float*)d_in[0];
    const float* coord = (const float*)d_in[1];
    const int*   knn   = (const int*)  d_in[2];
    const float* Wq = (const float*)d_in[3];  const float* bq = (const float*)d_in[4];  const float* bnq = (const float*)d_in[5];
    const float* Wk = (const float*)d_in[6];  const float* bk = (const float*)d_in[7];  const float* bnk = (const float*)d_in[8];
    const float* Wv = (const float*)d_in[9];  const float* bv = (const float*)d_in[10];
    const float* Wp1 = (const float*)d_in[11]; const float* bp1 = (const float*)d_in[12]; const float* bnp = (const float*)d_in[13];
    const float* Wp2 = (const float*)d_in[14]; const float* bp2 = (const float*)d_in[15];
    const float* Ww1 = (const float*)d_in[16]; const float* bw1 = (const float*)d_in[17]; const float* bnw = (const float*)d_in[18];
    const float* Ww2 = (const float*)d_in[19]; const float* bw2 = (const float*)d_in[20];
    float* out = (float*)d_out;

    int k1_smem = (BM * FS + 32 * WS + BM * C) * 4;
    cudaFuncSetAttribute(k1_qkv,  cudaFuncAttributeMaxDynamicSharedMemorySize, k1_smem);
    cudaFuncSetAttribute(k2_attn, cudaFuncAttributeMaxDynamicSharedMemorySize, (int)sizeof(K2S));

    prep_fold<<<1, 256>>>(bq, bnq, bk, bnk, bp1, bnp, bw1, bnw, bp2, Ww1);
    prep_At<<<16, 256>>>(Wp2, Ww1);
    prep_wp2t<<<C, C>>>(Wp2);
    k1_qkv<<<NPTS / BM, 256, k1_smem>>>(feat, Wq, Wk, Wv, bv, Ww1);
    k2_attn<<<NPTS / P, 256, sizeof(K2S)>>>(coord, knn, Wp1, bp2, Ww2, bw2, out);
}

// round 6
// speedup vs baseline: 1.4056x; 1.1144x over previous
#include <cuda_runtime.h>
#include <math.h>

#define NPTS 20000
#define KNN  16
#define C    256
#define G    16
#define EPS  1e-5f
#define P    4          // points per block in K2
#define BM   32         // feat rows per block in K1
#define CP   260        // padded row stride for hid
#define FS   260        // k1 feat_s stride (A-frag conflict-free)
#define LGS  20         // logit buffer row stride

typedef unsigned long long ull;

// ---------------- scratch (static device memory) ---------------------------
__device__ float    g_vall[NPTS * C];
__device__ float    g_qW[NPTS * G];
__device__ float    g_kW[NPTS * G];
__device__ unsigned g_wfrag[3 * 32 * 32 * 64];  // W q/k/v in mma B-frag layout (tf32)
__device__ unsigned g_afrag[32 * 2 * 64];       // (Wp2@Ww1) B-frag layout (tf32)
__device__ float    g_wp2t[C * C];              // Wp2^T: [c][k]
__device__ float    g_sq[C], g_tq[C];
__device__ float    g_sk[C], g_tk[C];
__device__ float    g_sp[C], g_tp[C];
__device__ float    g_sw[G], g_cw[G];

// ---------------- tf32 helper ----------------------------------------------
__device__ __forceinline__ unsigned f2tf(float x) {
    unsigned r;
    asm("cvt.rna.tf32.f32 %0, %1;" : "=r"(r) : "f"(x));
    return r;
}
#define MMA_TF32(acc, a0, a1, a2, a3, b0, b1)                                   \
    asm("mma.sync.aligned.m16n8k8.row.col.f32.tf32.tf32.f32 "                   \
        "{%0,%1,%2,%3},{%4,%5,%6,%7},{%8,%9},{%0,%1,%2,%3};"                    \
        : "+f"(acc.x), "+f"(acc.y), "+f"(acc.z), "+f"(acc.w)                    \
        : "r"(a0), "r"(a1), "r"(a2), "r"(a3), "r"(b0), "r"(b1))

// ---------------- prep kernels ---------------------------------------------
__global__ void prep_fold(const float* __restrict__ bq, const float* __restrict__ bnq,
                          const float* __restrict__ bk, const float* __restrict__ bnk,
                          const float* __restrict__ bp1, const float* __restrict__ bnp,
                          const float* __restrict__ bw1, const float* __restrict__ bnw,
                          const float* __restrict__ bp2, const float* __restrict__ ww1) {
    int t = threadIdx.x;
    if (t < C) {
        float s;
        s = bnq[t] * rsqrtf(bnq[3 * C + t] + EPS);
        g_sq[t] = s; g_tq[t] = (bq[t] - bnq[2 * C + t]) * s + bnq[C + t];
        s = bnk[t] * rsqrtf(bnk[3 * C + t] + EPS);
        g_sk[t] = s; g_tk[t] = (bk[t] - bnk[2 * C + t]) * s + bnk[C + t];
        s = bnp[t] * rsqrtf(bnp[3 * C + t] + EPS);
        g_sp[t] = s; g_tp[t] = (bp1[t] - bnp[2 * C + t]) * s + bnp[C + t];
    }
    if (t < G) {
        float s = bnw[t] * rsqrtf(bnw[3 * G + t] + EPS);
        float bp2w = 0.f;
        for (int c = 0; c < C; c++) bp2w += bp2[c] * ww1[c * G + t];
        g_sw[t] = s;
        g_cw[t] = (bw1[t] + bp2w - bnw[2 * G + t]) * s + bnw[G + t];
    }
}

// pack W (k-major 256x256) into mma B-fragment layout, tf32
__global__ void prep_wfrag(const float* __restrict__ W, unsigned* __restrict__ dst) {
    int kb = blockIdx.x;            // 0..31
    int i  = threadIdx.x;           // 0..1023
    int nb = i >> 5, lane = i & 31;
    int gid = lane >> 2, tig = lane & 3;
    int k0 = kb * 8 + tig, n = nb * 8 + gid;
    dst[((kb * 32 + nb) * 32 + lane) * 2 + 0] = f2tf(W[k0 * C + n]);
    dst[((kb * 32 + nb) * 32 + lane) * 2 + 1] = f2tf(W[(k0 + 4) * C + n]);
}

// A[k][g] = sum_c Wp2[k][c]*Ww1[c][g], packed into B-frag layout, tf32
__global__ void prep_afrag(const float* __restrict__ wp2, const float* __restrict__ ww1) {
    int idx  = blockIdx.x * 256 + threadIdx.x;   // 0..2047
    int lane = idx & 31, nbk = idx >> 5;
    int kb = nbk >> 1, nb = nbk & 1;
    int gid = lane >> 2, tig = lane & 3;
    int k0 = kb * 8 + tig, g = nb * 8 + gid;
    float s0 = 0.f, s1 = 0.f;
    #pragma unroll 4
    for (int c = 0; c < C; c++) {
        float w = ww1[c * G + g];
        s0 = fmaf(wp2[k0 * C + c],       w, s0);
        s1 = fmaf(wp2[(k0 + 4) * C + c], w, s1);
    }
    g_afrag[idx * 2 + 0] = f2tf(s0);
    g_afrag[idx * 2 + 1] = f2tf(s1);
}

__global__ void prep_wp2t(const float* __restrict__ wp2) {
    int k = blockIdx.x, c = threadIdx.x;
    g_wp2t[c * C + k] = wp2[k * C + c];
}

// ---------------- K1: q/k/v GEMM, TF32 mma, B-frags direct from gmem -------
// 8 warps; warp tile m32 x n32 (warp w owns cols w*32..w*32+31, all 32 rows).
__global__ __launch_bounds__(256, 2) void k1_qkv(
    const float* __restrict__ feat,
    const float* __restrict__ bv, const float* __restrict__ ww1) {
    extern __shared__ float sm[];
    float* feat_s = sm;                       // 32*FS
    float* ybuf   = sm + BM * FS;             // 32*256
    float* ww1s   = sm + BM * FS + BM * C;    // 256*16
    unsigned* featu = (unsigned*)feat_s;

    int t    = threadIdx.x;
    int r0b  = blockIdx.x * BM;
    int warp = t >> 5, lane = t & 31;
    int gid  = lane >> 2, tig = lane & 3;
    int n0   = warp * 32;

    // stage feat tile (tf32) and ww1
    for (int i = t; i < BM * C / 4; i += 256) {
        int r = i >> 6, c4 = (i & 63) * 4;
        float4 f = *(const float4*)&feat[(r0b + r) * C + c4];
        featu[r * FS + c4 + 0] = f2tf(f.x);
        featu[r * FS + c4 + 1] = f2tf(f.y);
        featu[r * FS + c4 + 2] = f2tf(f.z);
        featu[r * FS + c4 + 3] = f2tf(f.w);
    }
    for (int i = t; i < C * G; i += 256) ww1s[i] = ww1[i];
    __syncthreads();

    #pragma unroll 1
    for (int pass = 0; pass < 3; pass++) {
        const ull* wf = (const ull*)(g_wfrag + pass * (32 * 32 * 64));
        float4 acc[2][4];
        #pragma unroll
        for (int mt = 0; mt < 2; mt++)
            #pragma unroll
            for (int nt = 0; nt < 4; nt++) acc[mt][nt] = make_float4(0.f, 0.f, 0.f, 0.f);

        #pragma unroll 4
        for (int kb = 0; kb < 32; kb++) {
            unsigned a0 = featu[(gid)      * FS + kb * 8 + tig];
            unsigned a1 = featu[(gid + 8)  * FS + kb * 8 + tig];
            unsigned a2 = featu[(gid)      * FS + kb * 8 + tig + 4];
            unsigned a3 = featu[(gid + 8)  * FS + kb * 8 + tig + 4];
            unsigned a4 = featu[(gid + 16) * FS + kb * 8 + tig];
            unsigned a5 = featu[(gid + 24) * FS + kb * 8 + tig];
            unsigned a6 = featu[(gid + 16) * FS + kb * 8 + tig + 4];
            unsigned a7 = featu[(gid + 24) * FS + kb * 8 + tig + 4];
            #pragma unroll
            for (int nt = 0; nt < 4; nt++) {
                ull bb = wf[(kb * 32 + warp * 4 + nt) * 32 + lane];
                unsigned b0 = (unsigned)bb, b1 = (unsigned)(bb >> 32);
                MMA_TF32(acc[0][nt], a0, a1, a2, a3, b0, b1);
                MMA_TF32(acc[1][nt], a4, a5, a6, a7, b0, b1);
            }
        }

        if (pass == 2) {
            #pragma unroll
            for (int nt = 0; nt < 4; nt++) {
                int col = n0 + nt * 8 + tig * 2;
                float2 b2 = *(const float2*)&bv[col];
                #pragma unroll
                for (int mt = 0; mt < 2; mt++) {
                    int rA = r0b + mt * 16 + gid, rB = rA + 8;
                    *(float2*)&g_vall[rA * C + col] =
                        make_float2(acc[mt][nt].x + b2.x, acc[mt][nt].y + b2.y);
                    *(float2*)&g_vall[rB * C + col] =
                        make_float2(acc[mt][nt].z + b2.x, acc[mt][nt].w + b2.y);
                }
            }
        } else {
            const float* sA = (pass == 0) ? g_sq : g_sk;
            const float* tA = (pass == 0) ? g_tq : g_tk;
            #pragma unroll
            for (int nt = 0; nt < 4; nt++) {
                int col = n0 + nt * 8 + tig * 2;
                float2 s2 = *(const float2*)&sA[col];
                float2 t2 = *(const float2*)&tA[col];
                #pragma unroll
                for (int mt = 0; mt < 2; mt++) {
                    int rA = mt * 16 + gid, rB = rA + 8;
                    *(float2*)&ybuf[rA * C + col] = make_float2(
                        fmaxf(fmaf(acc[mt][nt].x, s2.x, t2.x), 0.f),
                        fmaxf(fmaf(acc[mt][nt].y, s2.y, t2.y), 0.f));
                    *(float2*)&ybuf[rB * C + col] = make_float2(
                        fmaxf(fmaf(acc[mt][nt].z, s2.x, t2.x), 0.f),
                        fmaxf(fmaf(acc[mt][nt].w, s2.y, t2.y), 0.f));
                }
            }
            __syncthreads();
            // projection to 16-dim: thread (rr, g) handles rows rr, rr+16
            int g_ = t & 15, rr = t >> 4;
            float p0 = 0.f, p1 = 0.f;
            #pragma unroll 4
            for (int k = 0; k < C; k += 4) {
                float4 ya = *(const float4*)&ybuf[rr * C + k];
                float4 yb = *(const float4*)&ybuf[(rr + 16) * C + k];
                float q0 = ww1s[(k + 0) * G + g_];
                float q1 = ww1s[(k + 1) * G + g_];
                float q2 = ww1s[(k + 2) * G + g_];
                float q3 = ww1s[(k + 3) * G + g_];
                p0 = fmaf(ya.x, q0, p0); p1 = fmaf(yb.x, q0, p1);
                p0 = fmaf(ya.y, q1, p0); p1 = fmaf(yb.y, q1, p1);
                p0 = fmaf(ya.z, q2, p0); p1 = fmaf(yb.z, q2, p1);
                p0 = fmaf(ya.w, q3, p0); p1 = fmaf(yb.w, q3, p1);
            }
            float* dst = (pass == 0) ? g_qW : g_kW;
            dst[(r0b + rr) * G + g_]      = p0;
            dst[(r0b + rr + 16) * G + g_] = p1;
            __syncthreads();   // ybuf reused next pass
        }
    }
}

// ---------------- K2: fused per-point grouped attention -------------------
struct K2S {
    float    hid[P * 16 * CP];   // becomes hw in place
    unsigned afrag[4096];        // A in B-frag layout (tf32)
    float    lg[64 * LGS];       // raw logits pre-activation (hid@A result)
    float    buf2[P * 16 * G];   // logits -> softmax weights
    float    pos[P * 16 * 4];
    float    wsum[P * G];
    float    mask[P * 16];
    int      idx[P * 16];
    float    ww2[G * G];
    float    bp2s[C];
    float    sw[G], cw[G], bw2s[G];
};

__global__ __launch_bounds__(256, 2) void k2_attn(
    const float* __restrict__ coord, const int* __restrict__ knn,
    const float* __restrict__ wp1,   const float* __restrict__ bp2,
    const float* __restrict__ ww2,   const float* __restrict__ bw2,
    float* __restrict__ out) {
    extern __shared__ char smraw[];
    K2S& S = *reinterpret_cast<K2S*>(smraw);
    int t  = threadIdx.x;
    int n0 = blockIdx.x * P;

    for (int i = t; i < 4096 / 4; i += 256)
        *(uint4*)&S.afrag[i * 4] = *(const uint4*)&g_afrag[i * 4];
    S.ww2[t]  = ww2[t];
    S.bp2s[t] = bp2[t];
    if (t < G) { S.sw[t] = g_sw[t]; S.cw[t] = g_cw[t]; S.bw2s[t] = bw2[t]; }

    // phase 1: gather idx / mask / pos
    if (t < P * 16) {
        int p = t >> 4, n = n0 + p;
        int id  = knn[n * KNN + (t & 15)];
        int ip1 = id + 1;
        float m = (float)((ip1 > 0) - (ip1 < 0));
        int sid = (id > 0) ? id : 0;
        S.idx[t]  = sid;
        S.mask[t] = m;
        #pragma unroll
        for (int d = 0; d < 3; d++)
            S.pos[t * 4 + d] = (coord[sid * 3 + d] - coord[n * 3 + d]) * m;
    }
    __syncthreads();

    // phase 2: hidden = relu(bn(pos @ Wp1 + bp1))
    {
        int c = t;
        float w0 = wp1[c], w1 = wp1[C + c], w2 = wp1[2 * C + c];
        float sc = g_sp[c], sh = g_tp[c];
        #pragma unroll 4
        for (int ps = 0; ps < P * 16; ps++) {
            float px = S.pos[ps * 4 + 0];
            float py = S.pos[ps * 4 + 1];
            float pz = S.pos[ps * 4 + 2];
            float h  = fmaf(px, w0, fmaf(py, w1, pz * w2));
            S.hid[ps * CP + c] = fmaxf(fmaf(h, sc, sh), 0.f);
        }
    }
    __syncthreads();

    // phase 3a: lg = hidden @ A via TF32 mma (8 warps: 4 m-tiles x 2 n-halves)
    {
        int w = t >> 5, lane = t & 31, gid = lane >> 2, tig = lane & 3;
        int m0 = (w & 3) * 16, nb = w >> 2;
        float4 acc = make_float4(0.f, 0.f, 0.f, 0.f);
        const ull* bf = (const ull*)S.afrag;
        #pragma unroll 4
        for (int kb = 0; kb < 32; kb++) {
            unsigned a0 = f2tf(S.hid[(m0 + gid)     * CP + kb * 8 + tig]);
            unsigned a1 = f2tf(S.hid[(m0 + gid + 8) * CP + kb * 8 + tig]);
            unsigned a2 = f2tf(S.hid[(m0 + gid)     * CP + kb * 8 + tig + 4]);
            unsigned a3 = f2tf(S.hid[(m0 + gid + 8) * CP + kb * 8 + tig + 4]);
            ull bb = bf[(kb * 2 + nb) * 32 + lane];
            unsigned b0 = (unsigned)bb, b1 = (unsigned)(bb >> 32);
            MMA_TF32(acc, a0, a1, a2, a3, b0, b1);
        }
        S.lg[(m0 + gid)     * LGS + nb * 8 + tig * 2]     = acc.x;
        S.lg[(m0 + gid)     * LGS + nb * 8 + tig * 2 + 1] = acc.y;
        S.lg[(m0 + gid + 8) * LGS + nb * 8 + tig * 2]     = acc.z;
        S.lg[(m0 + gid + 8) * LGS + nb * 8 + tig * 2 + 1] = acc.w;
    }
    __syncthreads();

    // phase 3b (64 threads): + lb, relu/sw/cw, @Ww2 -> buf2
    if (t < 64) {
        int r = t, p = r >> 4;
        float m = S.mask[r];
        int  id = S.idx[r];
        const float4* kw = (const float4*)&g_kW[id * G];
        const float4* qw = (const float4*)&g_qW[(n0 + p) * G];
        float u[16];
        #pragma unroll
        for (int q = 0; q < 4; q++) {
            float4 sv = *(const float4*)&S.lg[r * LGS + q * 4];
            float4 kv = kw[q], qv = qw[q];
            float4 lb;
            lb.x = fmaf(m, kv.x, -qv.x); lb.y = fmaf(m, kv.y, -qv.y);
            lb.z = fmaf(m, kv.z, -qv.z); lb.w = fmaf(m, kv.w, -qv.w);
            u[q*4+0] = fmaxf(fmaf(sv.x + lb.x, S.sw[q*4+0], S.cw[q*4+0]), 0.f);
            u[q*4+1] = fmaxf(fmaf(sv.y + lb.y, S.sw[q*4+1], S.cw[q*4+1]), 0.f);
            u[q*4+2] = fmaxf(fmaf(sv.z + lb.z, S.sw[q*4+2], S.cw[q*4+2]), 0.f);
            u[q*4+3] = fmaxf(fmaf(sv.w + lb.w, S.sw[q*4+3], S.cw[q*4+3]), 0.f);
        }
        #pragma unroll
        for (int g2 = 0; g2 < 16; g2++) {
            float acc = S.bw2s[g2];
            #pragma unroll
            for (int g = 0; g < 16; g++) acc = fmaf(u[g], S.ww2[g * 16 + g2], acc);
            S.buf2[r * 16 + g2] = acc;
        }
    }
    __syncthreads();

    // phase 4a: softmax over s per (p,g)
    if (t < P * G) {
        int p = t >> 4, g = t & 15;
        float mx = -1e30f;
        #pragma unroll
        for (int s = 0; s < 16; s++) mx = fmaxf(mx, S.buf2[(p * 16 + s) * 16 + g]);
        float e[16], sum = 0.f;
        #pragma unroll
        for (int s = 0; s < 16; s++) {
            e[s] = __expf(S.buf2[(p * 16 + s) * 16 + g] - mx);
            sum += e[s];
        }
        float inv = 1.f / sum, ws = 0.f;
        #pragma unroll
        for (int s = 0; s < 16; s++) {
            float w = e[s] * inv * S.mask[p * 16 + s];
            S.buf2[(p * 16 + s) * 16 + g] = w;
            ws += w;
        }
        S.wsum[t] = ws;
    }
    __syncthreads();

    // phase 4b: hw[p][g][c] = sum_s w[p][s][g]*hid[p][s][c]  (in place)
    {
        int p = t >> 6, c0 = (t & 63) * 4;
        float4 acc[16];
        #pragma unroll
        for (int g = 0; g < 16; g++) acc[g] = make_float4(0.f, 0.f, 0.f, 0.f);
        const float4* wv4 = (const float4*)S.buf2;
        #pragma unroll
        for (int s = 0; s < 16; s++) {
            float4 h = *(const float4*)&S.hid[(p * 16 + s) * CP + c0];
            #pragma unroll
            for (int q = 0; q < 4; q++) {
                float4 w = wv4[(p * 16 + s) * 4 + q];
                acc[q*4+0].x = fmaf(w.x, h.x, acc[q*4+0].x); acc[q*4+0].y = fmaf(w.x, h.y, acc[q*4+0].y);
                acc[q*4+0].z = fmaf(w.x, h.z, acc[q*4+0].z); acc[q*4+0].w = fmaf(w.x, h.w, acc[q*4+0].w);
                acc[q*4+1].x = fmaf(w.y, h.x, acc[q*4+1].x); acc[q*4+1].y = fmaf(w.y, h.y, acc[q*4+1].y);
                acc[q*4+1].z = fmaf(w.y, h.z, acc[q*4+1].z); acc[q*4+1].w = fmaf(w.y, h.w, acc[q*4+1].w);
                acc[q*4+2].x = fmaf(w.z, h.x, acc[q*4+2].x); acc[q*4+2].y = fmaf(w.z, h.y, acc[q*4+2].y);
                acc[q*4+2].z = fmaf(w.z, h.z, acc[q*4+2].z); acc[q*4+2].w = fmaf(w.z, h.w, acc[q*4+2].w);
                acc[q*4+3].x = fmaf(w.w, h.x, acc[q*4+3].x); acc[q*4+3].y = fmaf(w.w, h.y, acc[q*4+3].y);
                acc[q*4+3].z = fmaf(w.w, h.z, acc[q*4+3].z); acc[q*4+3].w = fmaf(w.w, h.w, acc[q*4+3].w);
            }
        }
        #pragma unroll
        for (int g = 0; g < 16; g++)
            *(float4*)&S.hid[(p * 16 + g) * CP + c0] = acc[g];
    }
    __syncthreads();

    // phase 5: out = v-gather + hw @ Wp2^T + bp2*wsum
    {
        int c = t, g = c >> 4;
        float b = S.bp2s[c];
        float acc0 = b * S.wsum[g],       acc1 = b * S.wsum[16 + g];
        float acc2 = b * S.wsum[32 + g],  acc3 = b * S.wsum[48 + g];

        #pragma unroll
        for (int s = 0; s < 16; s++) {
            int i0 = S.idx[s], i1 = S.idx[16 + s], i2 = S.idx[32 + s], i3 = S.idx[48 + s];
            float v0 = __ldg(&g_vall[i0 * C + c]);
            float v1 = __ldg(&g_vall[i1 * C + c]);
            float v2 = __ldg(&g_vall[i2 * C + c]);
            float v3 = __ldg(&g_vall[i3 * C + c]);
            acc0 = fmaf(S.buf2[(s)      * 16 + g], v0, acc0);
            acc1 = fmaf(S.buf2[(16 + s) * 16 + g], v1, acc1);
            acc2 = fmaf(S.buf2[(32 + s) * 16 + g], v2, acc2);
            acc3 = fmaf(S.buf2[(48 + s) * 16 + g], v3, acc3);
        }

        const float4* wpt = (const float4*)&g_wp2t[c * C];
        const float4* h0  = (const float4*)&S.hid[(g)      * CP];
        const float4* h1  = (const float4*)&S.hid[(16 + g) * CP];
        const float4* h2  = (const float4*)&S.hid[(32 + g) * CP];
        const float4* h3  = (const float4*)&S.hid[(48 + g) * CP];
        #pragma unroll 4
        for (int kb = 0; kb < 64; kb++) {
            float4 wp = wpt[kb];
            float4 a0 = h0[kb], a1 = h1[kb], a2 = h2[kb], a3 = h3[kb];
            acc0 = fmaf(wp.x, a0.x, acc0); acc0 = fmaf(wp.y, a0.y, acc0);
            acc0 = fmaf(wp.z, a0.z, acc0); acc0 = fmaf(wp.w, a0.w, acc0);
            acc1 = fmaf(wp.x, a1.x, acc1); acc1 = fmaf(wp.y, a1.y, acc1);
            acc1 = fmaf(wp.z, a1.z, acc1); acc1 = fmaf(wp.w, a1.w, acc1);
            acc2 = fmaf(wp.x, a2.x, acc2); acc2 = fmaf(wp.y, a2.y, acc2);
            acc2 = fmaf(wp.z, a2.z, acc2); acc2 = fmaf(wp.w, a2.w, acc2);
            acc3 = fmaf(wp.x, a3.x, acc3); acc3 = fmaf(wp.y, a3.y, acc3);
            acc3 = fmaf(wp.z, a3.z, acc3); acc3 = fmaf(wp.w, a3.w, acc3);
        }
        out[(n0 + 0) * C + c] = acc0;
        out[(n0 + 1) * C + c] = acc1;
        out[(n0 + 2) * C + c] = acc2;
        out[(n0 + 3) * C + c] = acc3;
    }
}

// ---------------- launch ----------------------------------------------------
extern "C" void kernel_launch(void* const* d_in, const int* in_sizes, int n_in,
                              void* d_out, int out_size) {
    (void)in_sizes; (void)n_in; (void)out_size;
    const float* feat  = (const float*)d_in[0];
    const float* coord = (const float*)d_in[1];
    const int*   knn   = (const int*)  d_in[2];
    const float* Wq = (const float*)d_in[3];  const float* bq = (const float*)d_in[4];  const float* bnq = (const float*)d_in[5];
    const float* Wk = (const float*)d_in[6];  const float* bk = (const float*)d_in[7];  const float* bnk = (const float*)d_in[8];
    const float* Wv = (const float*)d_in[9];  const float* bv = (const float*)d_in[10];
    const float* Wp1 = (const float*)d_in[11]; const float* bp1 = (const float*)d_in[12]; const float* bnp = (const float*)d_in[13];
    const float* Wp2 = (const float*)d_in[14]; const float* bp2 = (const float*)d_in[15];
    const float* Ww1 = (const float*)d_in[16]; const float* bw1 = (const float*)d_in[17]; const float* bnw = (const float*)d_in[18];
    const float* Ww2 = (const float*)d_in[19]; const float* bw2 = (const float*)d_in[20];
    float* out = (float*)d_out;

    int k1_smem = (BM * FS + BM * C + C * G) * 4;
    cudaFuncSetAttribute(k1_qkv,  cudaFuncAttributeMaxDynamicSharedMemorySize, k1_smem);
    cudaFuncSetAttribute(k2_attn, cudaFuncAttributeMaxDynamicSharedMemorySize, (int)sizeof(K2S));

    unsigned* wfrag;
    cudaGetSymbolAddress((void**)&wfrag, g_wfrag);

    prep_fold<<<1, 256>>>(bq, bnq, bk, bnk, bp1, bnp, bw1, bnw, bp2, Ww1);
    prep_wp2t<<<C, C>>>(Wp2);
    prep_afrag<<<8, 256>>>(Wp2, Ww1);
    prep_wfrag<<<32, 1024>>>(Wq, wfrag);
    prep_wfrag<<<32, 1024>>>(Wk, wfrag + 32 * 32 * 64);
    prep_wfrag<<<32, 1024>>>(Wv, wfrag + 2 * 32 * 32 * 64);
    k1_qkv<<<NPTS / BM, 256, k1_smem>>>(feat, bv, Ww1);
    k2_attn<<<NPTS / P, 256, sizeof(K2S)>>>(coord, knn, Wp1, bp2, Ww2, bw2, out);
}

// round 7
// speedup vs baseline: 1.6194x; 1.1521x over previous
#include <cuda_runtime.h>
#include <cuda_fp16.h>
#include <math.h>

#define NPTS 20000
#define KNN  16
#define C    256
#define G    16
#define EPS  1e-5f
#define P    4          // points per block in K2
#define BM   32         // feat rows per block in K1
#define FS   260        // k1 feat_s stride
#define HP   264        // k2 hid row stride in halves (132 words, ≡4 mod 32)
#define LGS  20         // logit buffer row stride

typedef unsigned long long ull;

// ---------------- scratch (static device memory) ---------------------------
__device__ float    g_vall[NPTS * C];
__device__ float    g_qW[NPTS * G];
__device__ float    g_kW[NPTS * G];
__device__ unsigned g_wfrag[3 * 32 * 32 * 64];  // W q/k/v tf32 B-frags (k1)
__device__ unsigned g_afrag16[2048];            // (Wp2@Ww1) fp16 B-frags (k2)
__device__ float    g_wp2t[C * C];              // Wp2^T: [c][k]
__device__ float    g_sq[C], g_tq[C];
__device__ float    g_sk[C], g_tk[C];
__device__ float    g_sp[C], g_tp[C];
__device__ float    g_sw[G], g_cw[G];

// ---------------- helpers ---------------------------------------------------
__device__ __forceinline__ unsigned f2tf(float x) {
    unsigned r;
    asm("cvt.rna.tf32.f32 %0, %1;" : "=r"(r) : "f"(x));
    return r;
}
#define MMA_TF32(acc, a0, a1, a2, a3, b0, b1)                                   \
    asm("mma.sync.aligned.m16n8k8.row.col.f32.tf32.tf32.f32 "                   \
        "{%0,%1,%2,%3},{%4,%5,%6,%7},{%8,%9},{%0,%1,%2,%3};"                    \
        : "+f"(acc.x), "+f"(acc.y), "+f"(acc.z), "+f"(acc.w)                    \
        : "r"(a0), "r"(a1), "r"(a2), "r"(a3), "r"(b0), "r"(b1))
#define MMA_F16(acc, a0, a1, a2, a3, b0, b1)                                    \
    asm("mma.sync.aligned.m16n8k16.row.col.f32.f16.f16.f32 "                    \
        "{%0,%1,%2,%3},{%4,%5,%6,%7},{%8,%9},{%0,%1,%2,%3};"                    \
        : "+f"(acc.x), "+f"(acc.y), "+f"(acc.z), "+f"(acc.w)                    \
        : "r"(a0), "r"(a1), "r"(a2), "r"(a3), "r"(b0), "r"(b1))

// ---------------- prep kernels ---------------------------------------------
__global__ void prep_fold(const float* __restrict__ bq, const float* __restrict__ bnq,
                          const float* __restrict__ bk, const float* __restrict__ bnk,
                          const float* __restrict__ bp1, const float* __restrict__ bnp,
                          const float* __restrict__ bw1, const float* __restrict__ bnw,
                          const float* __restrict__ bp2, const float* __restrict__ ww1) {
    int t = threadIdx.x;
    if (t < C) {
        float s;
        s = bnq[t] * rsqrtf(bnq[3 * C + t] + EPS);
        g_sq[t] = s; g_tq[t] = (bq[t] - bnq[2 * C + t]) * s + bnq[C + t];
        s = bnk[t] * rsqrtf(bnk[3 * C + t] + EPS);
        g_sk[t] = s; g_tk[t] = (bk[t] - bnk[2 * C + t]) * s + bnk[C + t];
        s = bnp[t] * rsqrtf(bnp[3 * C + t] + EPS);
        g_sp[t] = s; g_tp[t] = (bp1[t] - bnp[2 * C + t]) * s + bnp[C + t];
    }
    if (t < G) {
        float s = bnw[t] * rsqrtf(bnw[3 * G + t] + EPS);
        float bp2w = 0.f;
        for (int c = 0; c < C; c++) bp2w += bp2[c] * ww1[c * G + t];
        g_sw[t] = s;
        g_cw[t] = (bw1[t] + bp2w - bnw[2 * G + t]) * s + bnw[G + t];
    }
}

// pack W (k-major 256x256) into tf32 mma B-frag layout (k1)
__global__ void prep_wfrag(const float* __restrict__ W, unsigned* __restrict__ dst) {
    int kb = blockIdx.x;
    int i  = threadIdx.x;
    int nb = i >> 5, lane = i & 31;
    int gid = lane >> 2, tig = lane & 3;
    int k0 = kb * 8 + tig, n = nb * 8 + gid;
    dst[((kb * 32 + nb) * 32 + lane) * 2 + 0] = f2tf(W[k0 * C + n]);
    dst[((kb * 32 + nb) * 32 + lane) * 2 + 1] = f2tf(W[(k0 + 4) * C + n]);
}

// A[k][g] = sum_c Wp2[k][c]*Ww1[c][g], packed into fp16 m16n8k16 B-frags
__global__ void prep_afrag16(const float* __restrict__ wp2, const float* __restrict__ ww1) {
    int idx  = blockIdx.x * 256 + threadIdx.x;   // 0..1023
    int lane = idx & 31, knb = idx >> 5;
    int kb = knb >> 1, nb = knb & 1;
    int gid = lane >> 2, tig = lane & 3;
    int g  = nb * 8 + gid;
    int k0 = kb * 16 + tig * 2;
    float d0 = 0.f, d1 = 0.f, d2 = 0.f, d3 = 0.f;
    #pragma unroll 4
    for (int c = 0; c < C; c++) {
        float w = ww1[c * G + g];
        d0 = fmaf(wp2[(k0)     * C + c], w, d0);
        d1 = fmaf(wp2[(k0 + 1) * C + c], w, d1);
        d2 = fmaf(wp2[(k0 + 8) * C + c], w, d2);
        d3 = fmaf(wp2[(k0 + 9) * C + c], w, d3);
    }
    half2 b0 = __floats2half2_rn(d0, d1);
    half2 b1 = __floats2half2_rn(d2, d3);
    g_afrag16[idx * 2 + 0] = *(unsigned*)&b0;
    g_afrag16[idx * 2 + 1] = *(unsigned*)&b1;
}

__global__ void prep_wp2t(const float* __restrict__ wp2) {
    int k = blockIdx.x, c = threadIdx.x;
    g_wp2t[c * C + k] = wp2[k * C + c];
}

// ---------------- K1: q/k/v GEMM, TF32 mma (unchanged from R6) -------------
__global__ __launch_bounds__(256, 2) void k1_qkv(
    const float* __restrict__ feat,
    const float* __restrict__ bv, const float* __restrict__ ww1) {
    extern __shared__ float sm[];
    float* feat_s = sm;                       // 32*FS
    float* ybuf   = sm + BM * FS;             // 32*256
    float* ww1s   = sm + BM * FS + BM * C;    // 256*16
    unsigned* featu = (unsigned*)feat_s;

    int t    = threadIdx.x;
    int r0b  = blockIdx.x * BM;
    int warp = t >> 5, lane = t & 31;
    int gid  = lane >> 2, tig = lane & 3;
    int n0   = warp * 32;

    for (int i = t; i < BM * C / 4; i += 256) {
        int r = i >> 6, c4 = (i & 63) * 4;
        float4 f = *(const float4*)&feat[(r0b + r) * C + c4];
        featu[r * FS + c4 + 0] = f2tf(f.x);
        featu[r * FS + c4 + 1] = f2tf(f.y);
        featu[r * FS + c4 + 2] = f2tf(f.z);
        featu[r * FS + c4 + 3] = f2tf(f.w);
    }
    for (int i = t; i < C * G; i += 256) ww1s[i] = ww1[i];
    __syncthreads();

    #pragma unroll 1
    for (int pass = 0; pass < 3; pass++) {
        const ull* wf = (const ull*)(g_wfrag + pass * (32 * 32 * 64));
        float4 acc[2][4];
        #pragma unroll
        for (int mt = 0; mt < 2; mt++)
            #pragma unroll
            for (int nt = 0; nt < 4; nt++) acc[mt][nt] = make_float4(0.f, 0.f, 0.f, 0.f);

        #pragma unroll 4
        for (int kb = 0; kb < 32; kb++) {
            unsigned a0 = featu[(gid)      * FS + kb * 8 + tig];
            unsigned a1 = featu[(gid + 8)  * FS + kb * 8 + tig];
            unsigned a2 = featu[(gid)      * FS + kb * 8 + tig + 4];
            unsigned a3 = featu[(gid + 8)  * FS + kb * 8 + tig + 4];
            unsigned a4 = featu[(gid + 16) * FS + kb * 8 + tig];
            unsigned a5 = featu[(gid + 24) * FS + kb * 8 + tig];
            unsigned a6 = featu[(gid + 16) * FS + kb * 8 + tig + 4];
            unsigned a7 = featu[(gid + 24) * FS + kb * 8 + tig + 4];
            #pragma unroll
            for (int nt = 0; nt < 4; nt++) {
                ull bb = wf[(kb * 32 + warp * 4 + nt) * 32 + lane];
                unsigned b0 = (unsigned)bb, b1 = (unsigned)(bb >> 32);
                MMA_TF32(acc[0][nt], a0, a1, a2, a3, b0, b1);
                MMA_TF32(acc[1][nt], a4, a5, a6, a7, b0, b1);
            }
        }

        if (pass == 2) {
            #pragma unroll
            for (int nt = 0; nt < 4; nt++) {
                int col = n0 + nt * 8 + tig * 2;
                float2 b2 = *(const float2*)&bv[col];
                #pragma unroll
                for (int mt = 0; mt < 2; mt++) {
                    int rA = r0b + mt * 16 + gid, rB = rA + 8;
                    *(float2*)&g_vall[rA * C + col] =
                        make_float2(acc[mt][nt].x + b2.x, acc[mt][nt].y + b2.y);
                    *(float2*)&g_vall[rB * C + col] =
                        make_float2(acc[mt][nt].z + b2.x, acc[mt][nt].w + b2.y);
                }
            }
        } else {
            const float* sA = (pass == 0) ? g_sq : g_sk;
            const float* tA = (pass == 0) ? g_tq : g_tk;
            #pragma unroll
            for (int nt = 0; nt < 4; nt++) {
                int col = n0 + nt * 8 + tig * 2;
                float2 s2 = *(const float2*)&sA[col];
                float2 t2 = *(const float2*)&tA[col];
                #pragma unroll
                for (int mt = 0; mt < 2; mt++) {
                    int rA = mt * 16 + gid, rB = rA + 8;
                    *(float2*)&ybuf[rA * C + col] = make_float2(
                        fmaxf(fmaf(acc[mt][nt].x, s2.x, t2.x), 0.f),
                        fmaxf(fmaf(acc[mt][nt].y, s2.y, t2.y), 0.f));
                    *(float2*)&ybuf[rB * C + col] = make_float2(
                        fmaxf(fmaf(acc[mt][nt].z, s2.x, t2.x), 0.f),
                        fmaxf(fmaf(acc[mt][nt].w, s2.y, t2.y), 0.f));
                }
            }
            __syncthreads();
            int g_ = t & 15, rr = t >> 4;
            float p0 = 0.f, p1 = 0.f;
            #pragma unroll 4
            for (int k = 0; k < C; k += 4) {
                float4 ya = *(const float4*)&ybuf[rr * C + k];
                float4 yb = *(const float4*)&ybuf[(rr + 16) * C + k];
                float q0 = ww1s[(k + 0) * G + g_];
                float q1 = ww1s[(k + 1) * G + g_];
                float q2 = ww1s[(k + 2) * G + g_];
                float q3 = ww1s[(k + 3) * G + g_];
                p0 = fmaf(ya.x, q0, p0); p1 = fmaf(yb.x, q0, p1);
                p0 = fmaf(ya.y, q1, p0); p1 = fmaf(yb.y, q1, p1);
                p0 = fmaf(ya.z, q2, p0); p1 = fmaf(yb.z, q2, p1);
                p0 = fmaf(ya.w, q3, p0); p1 = fmaf(yb.w, q3, p1);
            }
            float* dst = (pass == 0) ? g_qW : g_kW;
            dst[(r0b + rr) * G + g_]      = p0;
            dst[(r0b + rr + 16) * G + g_] = p1;
            __syncthreads();
        }
    }
}

// ---------------- K2: fused per-point grouped attention (fp16 hid) ---------
struct K2S {
    unsigned short hid[P * 16 * HP];  // 33792 B; fp16; becomes hw in place
    unsigned afrag[2048];             // 8192 B fp16 B-frags
    float    lg[64 * LGS];            // 5120
    float    buf2[64 * G];            // 4096: logits -> weights
    float    pos[64 * 4];             // 1024
    float    wsum[P * G];
    float    mask[64];
    int      idx[64];
    float    ww2[G * G];
    float    sw[G], cw[G], bw2s[G];
};

__global__ __launch_bounds__(256, 3) void k2_attn(
    const float* __restrict__ coord, const int* __restrict__ knn,
    const float* __restrict__ wp1,   const float* __restrict__ bp2,
    const float* __restrict__ ww2,   const float* __restrict__ bw2,
    float* __restrict__ out) {
    extern __shared__ char smraw[];
    K2S& S = *reinterpret_cast<K2S*>(smraw);
    int t  = threadIdx.x;
    int n0 = blockIdx.x * P;

    for (int i = t; i < 512; i += 256)
        *(uint4*)&S.afrag[i * 4] = *(const uint4*)&g_afrag16[i * 4];
    S.ww2[t & 255] = ww2[t & 255];
    if (t < G) { S.sw[t] = g_sw[t]; S.cw[t] = g_cw[t]; S.bw2s[t] = bw2[t]; }

    // phase 1: gather idx / mask / pos
    if (t < 64) {
        int p = t >> 4, n = n0 + p;
        int id  = knn[n * KNN + (t & 15)];
        int ip1 = id + 1;
        float m = (float)((ip1 > 0) - (ip1 < 0));
        int sid = (id > 0) ? id : 0;
        S.idx[t]  = sid;
        S.mask[t] = m;
        #pragma unroll
        for (int d = 0; d < 3; d++)
            S.pos[t * 4 + d] = (coord[sid * 3 + d] - coord[n * 3 + d]) * m;
    }
    __syncthreads();

    // phase 2: hidden = relu(bn(pos @ Wp1 + bp1)) -> fp16; 2 channels/thread
    {
        int half_ = t >> 7;
        int cp = (t & 127) * 2;
        float2 w0 = *(const float2*)&wp1[cp];
        float2 w1 = *(const float2*)&wp1[C + cp];
        float2 w2 = *(const float2*)&wp1[2 * C + cp];
        float2 sc = *(const float2*)&g_sp[cp];
        float2 sh = *(const float2*)&g_tp[cp];
        #pragma unroll 4
        for (int ps = half_ * 32; ps < half_ * 32 + 32; ps++) {
            float px = S.pos[ps * 4 + 0];
            float py = S.pos[ps * 4 + 1];
            float pz = S.pos[ps * 4 + 2];
            float h0 = fmaf(px, w0.x, fmaf(py, w1.x, pz * w2.x));
            float h1 = fmaf(px, w0.y, fmaf(py, w1.y, pz * w2.y));
            h0 = fmaxf(fmaf(h0, sc.x, sh.x), 0.f);
            h1 = fmaxf(fmaf(h1, sc.y, sh.y), 0.f);
            *(half2*)&S.hid[ps * HP + cp] = __floats2half2_rn(h0, h1);
        }
    }
    __syncthreads();

    // phase 3a: lg = hidden @ A via fp16 mma m16n8k16
    {
        int w = t >> 5, lane = t & 31, gid = lane >> 2, tig = lane & 3;
        int m0 = (w & 3) * 16, nb = w >> 2;
        float4 acc = make_float4(0.f, 0.f, 0.f, 0.f);
        const ull* bf = (const ull*)S.afrag;
        #pragma unroll
        for (int kb = 0; kb < 16; kb++) {
            unsigned a0 = *(const unsigned*)&S.hid[(m0 + gid)     * HP + kb * 16 + tig * 2];
            unsigned a1 = *(const unsigned*)&S.hid[(m0 + gid + 8) * HP + kb * 16 + tig * 2];
            unsigned a2 = *(const unsigned*)&S.hid[(m0 + gid)     * HP + kb * 16 + tig * 2 + 8];
            unsigned a3 = *(const unsigned*)&S.hid[(m0 + gid + 8) * HP + kb * 16 + tig * 2 + 8];
            ull bb = bf[(kb * 2 + nb) * 32 + lane];
            unsigned b0 = (unsigned)bb, b1 = (unsigned)(bb >> 32);
            MMA_F16(acc, a0, a1, a2, a3, b0, b1);
        }
        S.lg[(m0 + gid)     * LGS + nb * 8 + tig * 2]     = acc.x;
        S.lg[(m0 + gid)     * LGS + nb * 8 + tig * 2 + 1] = acc.y;
        S.lg[(m0 + gid + 8) * LGS + nb * 8 + tig * 2]     = acc.z;
        S.lg[(m0 + gid + 8) * LGS + nb * 8 + tig * 2 + 1] = acc.w;
    }
    __syncthreads();

    // phase 3b (warps 0-1): + lb, relu/sw/cw, @Ww2 -> buf2
    if (t < 64) {
        int r = t, p = r >> 4;
        float m = S.mask[r];
        int  id = S.idx[r];
        const float4* kw = (const float4*)&g_kW[id * G];
        const float4* qw = (const float4*)&g_qW[(n0 + p) * G];
        float u[16];
        #pragma unroll
        for (int q = 0; q < 4; q++) {
            float4 sv = *(const float4*)&S.lg[r * LGS + q * 4];
            float4 kv = kw[q], qv = qw[q];
            float4 lb;
            lb.x = fmaf(m, kv.x, -qv.x); lb.y = fmaf(m, kv.y, -qv.y);
            lb.z = fmaf(m, kv.z, -qv.z); lb.w = fmaf(m, kv.w, -qv.w);
            u[q*4+0] = fmaxf(fmaf(sv.x + lb.x, S.sw[q*4+0], S.cw[q*4+0]), 0.f);
            u[q*4+1] = fmaxf(fmaf(sv.y + lb.y, S.sw[q*4+1], S.cw[q*4+1]), 0.f);
            u[q*4+2] = fmaxf(fmaf(sv.z + lb.z, S.sw[q*4+2], S.cw[q*4+2]), 0.f);
            u[q*4+3] = fmaxf(fmaf(sv.w + lb.w, S.sw[q*4+3], S.cw[q*4+3]), 0.f);
        }
        #pragma unroll
        for (int g2 = 0; g2 < 16; g2++) {
            float acc = S.bw2s[g2];
            #pragma unroll
            for (int g = 0; g < 16; g++) acc = fmaf(u[g], S.ww2[g * 16 + g2], acc);
            S.buf2[r * 16 + g2] = acc;
        }
        __syncwarp();
        // phase 4a (same warps; rows of each p stay within one warp):
        // softmax over s per (p,g)
        int pp = t >> 4, g = t & 15;
        float mx = -1e30f;
        #pragma unroll
        for (int s = 0; s < 16; s++) mx = fmaxf(mx, S.buf2[(pp * 16 + s) * 16 + g]);
        float e[16], sum = 0.f;
        #pragma unroll
        for (int s = 0; s < 16; s++) {
            e[s] = __expf(S.buf2[(pp * 16 + s) * 16 + g] - mx);
            sum += e[s];
        }
        float inv = 1.f / sum, ws = 0.f;
        #pragma unroll
        for (int s = 0; s < 16; s++) {
            float w = e[s] * inv * S.mask[pp * 16 + s];
            S.buf2[(pp * 16 + s) * 16 + g] = w;
            ws += w;
        }
        S.wsum[t] = ws;
    }
    __syncthreads();

    // phase 4b: hw[p][g][c] = sum_s w[p][s][g]*hid[p][s][c], in place (fp16)
    // 512 (p, 2-channel) slots; thread handles slot t and t+256 (disjoint p).
    {
        #pragma unroll
        for (int j = 0; j < 2; j++) {
            int si = t + j * 256;
            int p = si >> 7, cp = (si & 127) * 2;
            float2 acc[16];
            #pragma unroll
            for (int g = 0; g < 16; g++) acc[g] = make_float2(0.f, 0.f);
            #pragma unroll
            for (int s = 0; s < 16; s++) {
                float2 h = __half22float2(*(const half2*)&S.hid[(p * 16 + s) * HP + cp]);
                const float4* wr = (const float4*)&S.buf2[(p * 16 + s) * 16];
                #pragma unroll
                for (int q = 0; q < 4; q++) {
                    float4 w = wr[q];
                    acc[q*4+0].x = fmaf(w.x, h.x, acc[q*4+0].x); acc[q*4+0].y = fmaf(w.x, h.y, acc[q*4+0].y);
                    acc[q*4+1].x = fmaf(w.y, h.x, acc[q*4+1].x); acc[q*4+1].y = fmaf(w.y, h.y, acc[q*4+1].y);
                    acc[q*4+2].x = fmaf(w.z, h.x, acc[q*4+2].x); acc[q*4+2].y = fmaf(w.z, h.y, acc[q*4+2].y);
                    acc[q*4+3].x = fmaf(w.w, h.x, acc[q*4+3].x); acc[q*4+3].y = fmaf(w.w, h.y, acc[q*4+3].y);
                }
            }
            #pragma unroll
            for (int g = 0; g < 16; g++)
                *(half2*)&S.hid[(p * 16 + g) * HP + cp] = __floats2half2_rn(acc[g].x, acc[g].y);
        }
    }
    __syncthreads();

    // phase 5: out = v-gather + hw @ Wp2^T + bp2*wsum
    {
        int c = t, g = c >> 4;
        float b = __ldg(&bp2[c]);
        float acc0 = b * S.wsum[g],       acc1 = b * S.wsum[16 + g];
        float acc2 = b * S.wsum[32 + g],  acc3 = b * S.wsum[48 + g];

        #pragma unroll
        for (int s = 0; s < 16; s++) {
            int i0 = S.idx[s], i1 = S.idx[16 + s], i2 = S.idx[32 + s], i3 = S.idx[48 + s];
            float v0 = __ldg(&g_vall[i0 * C + c]);
            float v1 = __ldg(&g_vall[i1 * C + c]);
            float v2 = __ldg(&g_vall[i2 * C + c]);
            float v3 = __ldg(&g_vall[i3 * C + c]);
            acc0 = fmaf(S.buf2[(s)      * 16 + g], v0, acc0);
            acc1 = fmaf(S.buf2[(16 + s) * 16 + g], v1, acc1);
            acc2 = fmaf(S.buf2[(32 + s) * 16 + g], v2, acc2);
            acc3 = fmaf(S.buf2[(48 + s) * 16 + g], v3, acc3);
        }

        const float4* wpt = (const float4*)&g_wp2t[c * C];
        const unsigned short* r0 = &S.hid[(g)      * HP];
        const unsigned short* r1 = &S.hid[(16 + g) * HP];
        const unsigned short* r2 = &S.hid[(32 + g) * HP];
        const unsigned short* r3 = &S.hid[(48 + g) * HP];
        #pragma unroll 8
        for (int kb = 0; kb < 64; kb++) {
            float4 wp = wpt[kb];
            uint2 u0 = *(const uint2*)&r0[kb * 4];
            uint2 u1 = *(const uint2*)&r1[kb * 4];
            uint2 u2 = *(const uint2*)&r2[kb * 4];
            uint2 u3 = *(const uint2*)&r3[kb * 4];
            float2 a0 = __half22float2(*(half2*)&u0.x), b0 = __half22float2(*(half2*)&u0.y);
            float2 a1 = __half22float2(*(half2*)&u1.x), b1 = __half22float2(*(half2*)&u1.y);
            float2 a2 = __half22float2(*(half2*)&u2.x), b2 = __half22float2(*(half2*)&u2.y);
            float2 a3 = __half22float2(*(half2*)&u3.x), b3 = __half22float2(*(half2*)&u3.y);
            acc0 = fmaf(wp.x, a0.x, acc0); acc0 = fmaf(wp.y, a0.y, acc0);
            acc0 = fmaf(wp.z, b0.x, acc0); acc0 = fmaf(wp.w, b0.y, acc0);
            acc1 = fmaf(wp.x, a1.x, acc1); acc1 = fmaf(wp.y, a1.y, acc1);
            acc1 = fmaf(wp.z, b1.x, acc1); acc1 = fmaf(wp.w, b1.y, acc1);
            acc2 = fmaf(wp.x, a2.x, acc2); acc2 = fmaf(wp.y, a2.y, acc2);
            acc2 = fmaf(wp.z, b2.x, acc2); acc2 = fmaf(wp.w, b2.y, acc2);
            acc3 = fmaf(wp.x, a3.x, acc3); acc3 = fmaf(wp.y, a3.y, acc3);
            acc3 = fmaf(wp.z, b3.x, acc3); acc3 = fmaf(wp.w, b3.y, acc3);
        }
        out[(n0 + 0) * C + c] = acc0;
        out[(n0 + 1) * C + c] = acc1;
        out[(n0 + 2) * C + c] = acc2;
        out[(n0 + 3) * C + c] = acc3;
    }
}

// ---------------- launch ----------------------------------------------------
extern "C" void kernel_launch(void* const* d_in, const int* in_sizes, int n_in,
                              void* d_out, int out_size) {
    (void)in_sizes; (void)n_in; (void)out_size;
    const float* feat  = (const float*)d_in[0];
    const float* coord = (const float*)d_in[1];
    const int*   knn   = (const int*)  d_in[2];
    const float* Wq = (const float*)d_in[3];  const float* bq = (const float*)d_in[4];  const float* bnq = (const float*)d_in[5];
    const float* Wk = (const float*)d_in[6];  const float* bk = (const float*)d_in[7];  const float* bnk = (const float*)d_in[8];
    const float* Wv = (const float*)d_in[9];  const float* bv = (const float*)d_in[10];
    const float* Wp1 = (const float*)d_in[11]; const float* bp1 = (const float*)d_in[12]; const float* bnp = (const float*)d_in[13];
    const float* Wp2 = (const float*)d_in[14]; const float* bp2 = (const float*)d_in[15];
    const float* Ww1 = (const float*)d_in[16]; const float* bw1 = (const float*)d_in[17]; const float* bnw = (const float*)d_in[18];
    const float* Ww2 = (const float*)d_in[19]; const float* bw2 = (const float*)d_in[20];
    float* out = (float*)d_out;

    int k1_smem = (BM * FS + BM * C + C * G) * 4;
    cudaFuncSetAttribute(k1_qkv,  cudaFuncAttributeMaxDynamicSharedMemorySize, k1_smem);
    cudaFuncSetAttribute(k2_attn, cudaFuncAttributeMaxDynamicSharedMemorySize, (int)sizeof(K2S));

    unsigned* wfrag;
    cudaGetSymbolAddress((void**)&wfrag, g_wfrag);

    prep_fold<<<1, 256>>>(bq, bnq, bk, bnk, bp1, bnp, bw1, bnw, bp2, Ww1);
    prep_wp2t<<<C, C>>>(Wp2);
    prep_afrag16<<<4, 256>>>(Wp2, Ww1);
    prep_wfrag<<<32, 1024>>>(Wq, wfrag);
    prep_wfrag<<<32, 1024>>>(Wk, wfrag + 32 * 32 * 64);
    prep_wfrag<<<32, 1024>>>(Wv, wfrag + 2 * 32 * 32 * 64);
    k1_qkv<<<NPTS / BM, 256, k1_smem>>>(feat, bv, Ww1);
    k2_attn<<<NPTS / P, 256, sizeof(K2S)>>>(coord, knn, Wp1, bp2, Ww2, bw2, out);
}

// round 8
// speedup vs baseline: 1.6745x; 1.0341x over previous
#include <cuda_runtime.h>
#include <cuda_fp16.h>
#include <math.h>

#define NPTS 20000
#define KNN  16
#define C    256
#define G    16
#define EPS  1e-5f
#define P    4          // points per block in K2
#define BM   32         // feat rows per block in K1
#define FS   260        // k1 feat_s stride (words)
#define YS   260        // k1 ybuf stride (words) - conflict-free A-frag loads
#define HP   264        // k2 hid row stride in halves
#define LGS  20         // logit buffer row stride

typedef unsigned long long ull;

// ---------------- scratch (static device memory) ---------------------------
__device__ __half   g_vall16[NPTS * C];         // v_all, fp16
__device__ float    g_qW[NPTS * G];
__device__ float    g_kW[NPTS * G];
__device__ unsigned g_wfrag[3 * 32 * 32 * 64];  // W q/k/v tf32 B-frags (k1)
__device__ unsigned g_w1frag[4096];             // ww1 tf32 B-frags (k1 projection)
__device__ unsigned g_afrag16[2048];            // (Wp2@Ww1) fp16 B-frags (k2)
__device__ float    g_wp2t[C * C];              // Wp2^T: [c][k]
__device__ float    g_sq[C], g_tq[C];
__device__ float    g_sk[C], g_tk[C];
__device__ float    g_sp[C], g_tp[C];
__device__ float    g_sw[G], g_cw[G];

// ---------------- helpers ---------------------------------------------------
__device__ __forceinline__ unsigned f2tf(float x) {
    unsigned r;
    asm("cvt.rna.tf32.f32 %0, %1;" : "=r"(r) : "f"(x));
    return r;
}
__device__ __forceinline__ unsigned smem_u32(const void* p) {
    unsigned r;
    asm("{ .reg .u64 t; cvta.to.shared.u64 t, %1; cvt.u32.u64 %0, t; }"
        : "=r"(r) : "l"(p));
    return r;
}
#define CP_ASYNC16(dst, src) \
    asm volatile("cp.async.ca.shared.global [%0], [%1], 16;" :: "r"(dst), "l"(src))
#define MMA_TF32(acc, a0, a1, a2, a3, b0, b1)                                   \
    asm("mma.sync.aligned.m16n8k8.row.col.f32.tf32.tf32.f32 "                   \
        "{%0,%1,%2,%3},{%4,%5,%6,%7},{%8,%9},{%0,%1,%2,%3};"                    \
        : "+f"(acc.x), "+f"(acc.y), "+f"(acc.z), "+f"(acc.w)                    \
        : "r"(a0), "r"(a1), "r"(a2), "r"(a3), "r"(b0), "r"(b1))
#define MMA_F16(acc, a0, a1, a2, a3, b0, b1)                                    \
    asm("mma.sync.aligned.m16n8k16.row.col.f32.f16.f16.f32 "                    \
        "{%0,%1,%2,%3},{%4,%5,%6,%7},{%8,%9},{%0,%1,%2,%3};"                    \
        : "+f"(acc.x), "+f"(acc.y), "+f"(acc.z), "+f"(acc.w)                    \
        : "r"(a0), "r"(a1), "r"(a2), "r"(a3), "r"(b0), "r"(b1))

// ---------------- prep kernels ---------------------------------------------
__global__ void prep_fold(const float* __restrict__ bq, const float* __restrict__ bnq,
                          const float* __restrict__ bk, const float* __restrict__ bnk,
                          const float* __restrict__ bp1, const float* __restrict__ bnp,
                          const float* __restrict__ bw1, const float* __restrict__ bnw,
                          const float* __restrict__ bp2, const float* __restrict__ ww1) {
    int t = threadIdx.x;
    if (t < C) {
        float s;
        s = bnq[t] * rsqrtf(bnq[3 * C + t] + EPS);
        g_sq[t] = s; g_tq[t] = (bq[t] - bnq[2 * C + t]) * s + bnq[C + t];
        s = bnk[t] * rsqrtf(bnk[3 * C + t] + EPS);
        g_sk[t] = s; g_tk[t] = (bk[t] - bnk[2 * C + t]) * s + bnk[C + t];
        s = bnp[t] * rsqrtf(bnp[3 * C + t] + EPS);
        g_sp[t] = s; g_tp[t] = (bp1[t] - bnp[2 * C + t]) * s + bnp[C + t];
    }
    if (t < G) {
        float s = bnw[t] * rsqrtf(bnw[3 * G + t] + EPS);
        float bp2w = 0.f;
        for (int c = 0; c < C; c++) bp2w += bp2[c] * ww1[c * G + t];
        g_sw[t] = s;
        g_cw[t] = (bw1[t] + bp2w - bnw[2 * G + t]) * s + bnw[G + t];
    }
}

// pack W (k-major 256x256) into tf32 mma B-frag layout (k1 main GEMM)
__global__ void prep_wfrag(const float* __restrict__ W, unsigned* __restrict__ dst) {
    int kb = blockIdx.x;
    int i  = threadIdx.x;
    int nb = i >> 5, lane = i & 31;
    int gid = lane >> 2, tig = lane & 3;
    int k0 = kb * 8 + tig, n = nb * 8 + gid;
    dst[((kb * 32 + nb) * 32 + lane) * 2 + 0] = f2tf(W[k0 * C + n]);
    dst[((kb * 32 + nb) * 32 + lane) * 2 + 1] = f2tf(W[(k0 + 4) * C + n]);
}

// pack ww1 (256x16) into tf32 B-frags (k1 projection)
__global__ void prep_w1frag(const float* __restrict__ ww1) {
    int idx  = blockIdx.x * 256 + threadIdx.x;   // 0..2047
    int lane = idx & 31, knb = idx >> 5;
    int kb = knb >> 1, nb = knb & 1;
    int gid = lane >> 2, tig = lane & 3;
    int n  = nb * 8 + gid;
    int k0 = kb * 8 + tig;
    g_w1frag[idx * 2 + 0] = f2tf(ww1[k0 * G + n]);
    g_w1frag[idx * 2 + 1] = f2tf(ww1[(k0 + 4) * G + n]);
}

// A[k][g] = sum_c Wp2[k][c]*Ww1[c][g], packed into fp16 m16n8k16 B-frags
__global__ void prep_afrag16(const float* __restrict__ wp2, const float* __restrict__ ww1) {
    int idx  = blockIdx.x * 256 + threadIdx.x;   // 0..1023
    int lane = idx & 31, knb = idx >> 5;
    int kb = knb >> 1, nb = knb & 1;
    int gid = lane >> 2, tig = lane & 3;
    int g  = nb * 8 + gid;
    int k0 = kb * 16 + tig * 2;
    float d0 = 0.f, d1 = 0.f, d2 = 0.f, d3 = 0.f;
    #pragma unroll 4
    for (int c = 0; c < C; c++) {
        float w = ww1[c * G + g];
        d0 = fmaf(wp2[(k0)     * C + c], w, d0);
        d1 = fmaf(wp2[(k0 + 1) * C + c], w, d1);
        d2 = fmaf(wp2[(k0 + 8) * C + c], w, d2);
        d3 = fmaf(wp2[(k0 + 9) * C + c], w, d3);
    }
    half2 b0 = __floats2half2_rn(d0, d1);
    half2 b1 = __floats2half2_rn(d2, d3);
    g_afrag16[idx * 2 + 0] = *(unsigned*)&b0;
    g_afrag16[idx * 2 + 1] = *(unsigned*)&b1;
}

__global__ void prep_wp2t(const float* __restrict__ wp2) {
    int k = blockIdx.x, c = threadIdx.x;
    g_wp2t[c * C + k] = wp2[k * C + c];
}

// ---------------- K1: q/k/v GEMM + projection, all TF32 mma ----------------
__global__ __launch_bounds__(256, 2) void k1_qkv(
    const float* __restrict__ feat, const float* __restrict__ bv) {
    extern __shared__ float sm[];
    float* feat_s = sm;                            // 32*FS
    float* ybuf   = sm + BM * FS;                  // 32*YS
    unsigned* ww1f = (unsigned*)(sm + BM * FS + BM * YS);  // 4096 unsigned
    unsigned* featu = (unsigned*)feat_s;

    int t    = threadIdx.x;
    int r0b  = blockIdx.x * BM;
    int warp = t >> 5, lane = t & 31;
    int gid  = lane >> 2, tig = lane & 3;
    int n0   = warp * 32;

    for (int i = t; i < BM * C / 4; i += 256) {
        int r = i >> 6, c4 = (i & 63) * 4;
        float4 f = *(const float4*)&feat[(r0b + r) * C + c4];
        featu[r * FS + c4 + 0] = f2tf(f.x);
        featu[r * FS + c4 + 1] = f2tf(f.y);
        featu[r * FS + c4 + 2] = f2tf(f.z);
        featu[r * FS + c4 + 3] = f2tf(f.w);
    }
    for (int i = t; i < 1024; i += 256)
        *(uint4*)&ww1f[i * 4] = *(const uint4*)&g_w1frag[i * 4];
    __syncthreads();

    #pragma unroll 1
    for (int pass = 0; pass < 3; pass++) {
        const ull* wf = (const ull*)(g_wfrag + pass * (32 * 32 * 64));
        float4 acc[2][4];
        #pragma unroll
        for (int mt = 0; mt < 2; mt++)
            #pragma unroll
            for (int nt = 0; nt < 4; nt++) acc[mt][nt] = make_float4(0.f, 0.f, 0.f, 0.f);

        #pragma unroll 4
        for (int kb = 0; kb < 32; kb++) {
            unsigned a0 = featu[(gid)      * FS + kb * 8 + tig];
            unsigned a1 = featu[(gid + 8)  * FS + kb * 8 + tig];
            unsigned a2 = featu[(gid)      * FS + kb * 8 + tig + 4];
            unsigned a3 = featu[(gid + 8)  * FS + kb * 8 + tig + 4];
            unsigned a4 = featu[(gid + 16) * FS + kb * 8 + tig];
            unsigned a5 = featu[(gid + 24) * FS + kb * 8 + tig];
            unsigned a6 = featu[(gid + 16) * FS + kb * 8 + tig + 4];
            unsigned a7 = featu[(gid + 24) * FS + kb * 8 + tig + 4];
            #pragma unroll
            for (int nt = 0; nt < 4; nt++) {
                ull bb = wf[(kb * 32 + warp * 4 + nt) * 32 + lane];
                unsigned b0 = (unsigned)bb, b1 = (unsigned)(bb >> 32);
                MMA_TF32(acc[0][nt], a0, a1, a2, a3, b0, b1);
                MMA_TF32(acc[1][nt], a4, a5, a6, a7, b0, b1);
            }
        }

        if (pass == 2) {
            #pragma unroll
            for (int nt = 0; nt < 4; nt++) {
                int col = n0 + nt * 8 + tig * 2;
                float2 b2 = *(const float2*)&bv[col];
                #pragma unroll
                for (int mt = 0; mt < 2; mt++) {
                    int rA = r0b + mt * 16 + gid, rB = rA + 8;
                    *(half2*)&g_vall16[rA * C + col] =
                        __floats2half2_rn(acc[mt][nt].x + b2.x, acc[mt][nt].y + b2.y);
                    *(half2*)&g_vall16[rB * C + col] =
                        __floats2half2_rn(acc[mt][nt].z + b2.x, acc[mt][nt].w + b2.y);
                }
            }
        } else {
            const float* sA = (pass == 0) ? g_sq : g_sk;
            const float* tA = (pass == 0) ? g_tq : g_tk;
            #pragma unroll
            for (int nt = 0; nt < 4; nt++) {
                int col = n0 + nt * 8 + tig * 2;
                float2 s2 = *(const float2*)&sA[col];
                float2 t2 = *(const float2*)&tA[col];
                #pragma unroll
                for (int mt = 0; mt < 2; mt++) {
                    int rA = mt * 16 + gid, rB = rA + 8;
                    *(float2*)&ybuf[rA * YS + col] = make_float2(
                        fmaxf(fmaf(acc[mt][nt].x, s2.x, t2.x), 0.f),
                        fmaxf(fmaf(acc[mt][nt].y, s2.y, t2.y), 0.f));
                    *(float2*)&ybuf[rB * YS + col] = make_float2(
                        fmaxf(fmaf(acc[mt][nt].z, s2.x, t2.x), 0.f),
                        fmaxf(fmaf(acc[mt][nt].w, s2.y, t2.y), 0.f));
                }
            }
            __syncthreads();
            // projection y @ ww1 via tf32 mma: 4 warps (m 2 x n 2 tiles)
            if (warp < 4) {
                int m0p = (warp & 1) * 16, nbp = warp >> 1;
                float4 pa = make_float4(0.f, 0.f, 0.f, 0.f);
                #pragma unroll 8
                for (int kb = 0; kb < 32; kb++) {
                    unsigned a0 = f2tf(ybuf[(m0p + gid)     * YS + kb * 8 + tig]);
                    unsigned a1 = f2tf(ybuf[(m0p + gid + 8) * YS + kb * 8 + tig]);
                    unsigned a2 = f2tf(ybuf[(m0p + gid)     * YS + kb * 8 + tig + 4]);
                    unsigned a3 = f2tf(ybuf[(m0p + gid + 8) * YS + kb * 8 + tig + 4]);
                    ull bb = *(const ull*)&ww1f[((kb * 2 + nbp) * 32 + lane) * 2];
                    MMA_TF32(pa, a0, a1, a2, a3, (unsigned)bb, (unsigned)(bb >> 32));
                }
                float* dst = (pass == 0) ? g_qW : g_kW;
                int col = nbp * 8 + tig * 2;
                dst[(r0b + m0p + gid)     * G + col]     = pa.x;
                dst[(r0b + m0p + gid)     * G + col + 1] = pa.y;
                dst[(r0b + m0p + gid + 8) * G + col]     = pa.z;
                dst[(r0b + m0p + gid + 8) * G + col + 1] = pa.w;
            }
            __syncthreads();   // ybuf reused next pass
        }
    }
}

// ---------------- K2: fused per-point grouped attention -------------------
struct K2S {
    unsigned short hid[P * 16 * HP];  // 33792 B; fp16; becomes hw in place
    unsigned afrag[2048];             // 8192 B fp16 B-frags
    float    lg[64 * LGS];            // 5120
    float    buf2[64 * G];            // 4096: logits -> weights
    float    vterm[4 * 256];          // 4096: v-gather partials
    float    kwq[64 * 16];            // 4096: prefetched kW rows
    float    qwb[4 * 16];             // 256:  prefetched qW rows
    float    pos[64 * 4];             // 1024
    float    wsum[P * G];
    float    mask[64];
    int      idx[64];
    float    ww2[G * G];
    float    sw[G], cw[G], bw2s[G];
};

__global__ __launch_bounds__(256, 3) void k2_attn(
    const float* __restrict__ coord, const int* __restrict__ knn,
    const float* __restrict__ wp1,   const float* __restrict__ bp2,
    const float* __restrict__ ww2,   const float* __restrict__ bw2,
    float* __restrict__ out) {
    extern __shared__ char smraw[];
    K2S& S = *reinterpret_cast<K2S*>(smraw);
    int t  = threadIdx.x;
    int n0 = blockIdx.x * P;

    for (int i = t; i < 512; i += 256)
        *(uint4*)&S.afrag[i * 4] = *(const uint4*)&g_afrag16[i * 4];
    S.ww2[t] = ww2[t];
    if (t < G) { S.sw[t] = g_sw[t]; S.cw[t] = g_cw[t]; S.bw2s[t] = bw2[t]; }

    // phase 1: gather idx / mask / pos + cp.async prefetch of kW/qW rows
    if (t < 64) {
        int p = t >> 4, n = n0 + p;
        int id  = knn[n * KNN + (t & 15)];
        int ip1 = id + 1;
        float m = (float)((ip1 > 0) - (ip1 < 0));
        int sid = (id > 0) ? id : 0;
        S.idx[t]  = sid;
        S.mask[t] = m;
        #pragma unroll
        for (int d = 0; d < 3; d++)
            S.pos[t * 4 + d] = (coord[sid * 3 + d] - coord[n * 3 + d]) * m;
        unsigned d0 = smem_u32(&S.kwq[t * 16]);
        const float* s0 = &g_kW[sid * G];
        #pragma unroll
        for (int j = 0; j < 4; j++) CP_ASYNC16(d0 + j * 16, s0 + j * 4);
        if (t < 4) {
            unsigned d1 = smem_u32(&S.qwb[t * 16]);
            const float* s1 = &g_qW[(n0 + t) * G];
            #pragma unroll
            for (int j = 0; j < 4; j++) CP_ASYNC16(d1 + j * 16, s1 + j * 4);
        }
        asm volatile("cp.async.commit_group;");
    }
    __syncthreads();

    // phase 2: hidden = relu(bn(pos @ Wp1 + bp1)) -> fp16
    {
        int half_ = t >> 7;
        int cp = (t & 127) * 2;
        float2 w0 = *(const float2*)&wp1[cp];
        float2 w1 = *(const float2*)&wp1[C + cp];
        float2 w2 = *(const float2*)&wp1[2 * C + cp];
        float2 sc = *(const float2*)&g_sp[cp];
        float2 sh = *(const float2*)&g_tp[cp];
        #pragma unroll 4
        for (int ps = half_ * 32; ps < half_ * 32 + 32; ps++) {
            float px = S.pos[ps * 4 + 0];
            float py = S.pos[ps * 4 + 1];
            float pz = S.pos[ps * 4 + 2];
            float h0 = fmaf(px, w0.x, fmaf(py, w1.x, pz * w2.x));
            float h1 = fmaf(px, w0.y, fmaf(py, w1.y, pz * w2.y));
            h0 = fmaxf(fmaf(h0, sc.x, sh.x), 0.f);
            h1 = fmaxf(fmaf(h1, sc.y, sh.y), 0.f);
            *(half2*)&S.hid[ps * HP + cp] = __floats2half2_rn(h0, h1);
        }
    }
    __syncthreads();

    // phase 3a: lg = hidden @ A via fp16 mma m16n8k16
    {
        int w = t >> 5, lane = t & 31, gid = lane >> 2, tig = lane & 3;
        int m0 = (w & 3) * 16, nb = w >> 2;
        float4 acc = make_float4(0.f, 0.f, 0.f, 0.f);
        const ull* bf = (const ull*)S.afrag;
        #pragma unroll
        for (int kb = 0; kb < 16; kb++) {
            unsigned a0 = *(const unsigned*)&S.hid[(m0 + gid)     * HP + kb * 16 + tig * 2];
            unsigned a1 = *(const unsigned*)&S.hid[(m0 + gid + 8) * HP + kb * 16 + tig * 2];
            unsigned a2 = *(const unsigned*)&S.hid[(m0 + gid)     * HP + kb * 16 + tig * 2 + 8];
            unsigned a3 = *(const unsigned*)&S.hid[(m0 + gid + 8) * HP + kb * 16 + tig * 2 + 8];
            ull bb = bf[(kb * 2 + nb) * 32 + lane];
            unsigned b0 = (unsigned)bb, b1 = (unsigned)(bb >> 32);
            MMA_F16(acc, a0, a1, a2, a3, b0, b1);
        }
        S.lg[(m0 + gid)     * LGS + nb * 8 + tig * 2]     = acc.x;
        S.lg[(m0 + gid)     * LGS + nb * 8 + tig * 2 + 1] = acc.y;
        S.lg[(m0 + gid + 8) * LGS + nb * 8 + tig * 2]     = acc.z;
        S.lg[(m0 + gid + 8) * LGS + nb * 8 + tig * 2 + 1] = acc.w;
    }
    __syncthreads();

    // phase 3b (warps 0-1): + lb, relu/sw/cw, @Ww2 -> buf2; then 4a softmax
    if (t < 64) {
        asm volatile("cp.async.wait_group 0;" ::: "memory");
        int r = t, p = r >> 4;
        float m = S.mask[r];
        const float4* kw = (const float4*)&S.kwq[r * 16];
        const float4* qw = (const float4*)&S.qwb[p * 16];
        float u[16];
        #pragma unroll
        for (int q = 0; q < 4; q++) {
            float4 sv = *(const float4*)&S.lg[r * LGS + q * 4];
            float4 kv = kw[q], qv = qw[q];
            float4 lb;
            lb.x = fmaf(m, kv.x, -qv.x); lb.y = fmaf(m, kv.y, -qv.y);
            lb.z = fmaf(m, kv.z, -qv.z); lb.w = fmaf(m, kv.w, -qv.w);
            u[q*4+0] = fmaxf(fmaf(sv.x + lb.x, S.sw[q*4+0], S.cw[q*4+0]), 0.f);
            u[q*4+1] = fmaxf(fmaf(sv.y + lb.y, S.sw[q*4+1], S.cw[q*4+1]), 0.f);
            u[q*4+2] = fmaxf(fmaf(sv.z + lb.z, S.sw[q*4+2], S.cw[q*4+2]), 0.f);
            u[q*4+3] = fmaxf(fmaf(sv.w + lb.w, S.sw[q*4+3], S.cw[q*4+3]), 0.f);
        }
        #pragma unroll
        for (int g2 = 0; g2 < 16; g2++) {
            float acc = S.bw2s[g2];
            #pragma unroll
            for (int g = 0; g < 16; g++) acc = fmaf(u[g], S.ww2[g * 16 + g2], acc);
            S.buf2[r * 16 + g2] = acc;
        }
        __syncwarp();
        // phase 4a: softmax over s per (p,g)
        int pp = t >> 4, g = t & 15;
        float mx = -1e30f;
        #pragma unroll
        for (int s = 0; s < 16; s++) mx = fmaxf(mx, S.buf2[(pp * 16 + s) * 16 + g]);
        float e[16], sum = 0.f;
        #pragma unroll
        for (int s = 0; s < 16; s++) {
            e[s] = __expf(S.buf2[(pp * 16 + s) * 16 + g] - mx);
            sum += e[s];
        }
        float inv = 1.f / sum, ws = 0.f;
        #pragma unroll
        for (int s = 0; s < 16; s++) {
            float w = e[s] * inv * S.mask[pp * 16 + s];
            S.buf2[(pp * 16 + s) * 16 + g] = w;
            ws += w;
        }
        S.wsum[t] = ws;
    }
    __syncthreads();

    // phase 4: (A) v-gather partials (gmem fp16) and (B) hw in place (fp16)
    // disjoint memory: A reads g_vall16/buf2 writes vterm; B reads hid/buf2
    // writes hid.
    {
        // ---- A: v-term for 2 points x 2 columns ----
        int ph = t >> 7, cp = t & 127;
        int c0 = cp * 2, gA = cp >> 3;
        int p0 = ph * 2, p1 = p0 + 1;
        float2 a0 = make_float2(0.f, 0.f), a1 = make_float2(0.f, 0.f);
        #pragma unroll
        for (int s = 0; s < 16; s++) {
            float w0 = S.buf2[(p0 * 16 + s) * 16 + gA];
            float w1 = S.buf2[(p1 * 16 + s) * 16 + gA];
            float2 v0 = __half22float2(*(const half2*)&g_vall16[S.idx[p0 * 16 + s] * C + c0]);
            float2 v1 = __half22float2(*(const half2*)&g_vall16[S.idx[p1 * 16 + s] * C + c0]);
            a0.x = fmaf(w0, v0.x, a0.x); a0.y = fmaf(w0, v0.y, a0.y);
            a1.x = fmaf(w1, v1.x, a1.x); a1.y = fmaf(w1, v1.y, a1.y);
        }
        *(float2*)&S.vterm[p0 * 256 + c0] = a0;
        *(float2*)&S.vterm[p1 * 256 + c0] = a1;

        // ---- B: hw[p][g][c] = sum_s w*hid, in place, 2 slots ----
        #pragma unroll
        for (int j = 0; j < 2; j++) {
            int si = t + j * 256;
            int p = si >> 7, cq = (si & 127) * 2;
            float2 acc[16];
            #pragma unroll
            for (int g = 0; g < 16; g++) acc[g] = make_float2(0.f, 0.f);
            #pragma unroll
            for (int s = 0; s < 16; s++) {
                float2 h = __half22float2(*(const half2*)&S.hid[(p * 16 + s) * HP + cq]);
                const float4* wr = (const float4*)&S.buf2[(p * 16 + s) * 16];
                #pragma unroll
                for (int q = 0; q < 4; q++) {
                    float4 w = wr[q];
                    acc[q*4+0].x = fmaf(w.x, h.x, acc[q*4+0].x); acc[q*4+0].y = fmaf(w.x, h.y, acc[q*4+0].y);
                    acc[q*4+1].x = fmaf(w.y, h.x, acc[q*4+1].x); acc[q*4+1].y = fmaf(w.y, h.y, acc[q*4+1].y);
                    acc[q*4+2].x = fmaf(w.z, h.x, acc[q*4+2].x); acc[q*4+2].y = fmaf(w.z, h.y, acc[q*4+2].y);
                    acc[q*4+3].x = fmaf(w.w, h.x, acc[q*4+3].x); acc[q*4+3].y = fmaf(w.w, h.y, acc[q*4+3].y);
                }
            }
            #pragma unroll
            for (int g = 0; g < 16; g++)
                *(half2*)&S.hid[(p * 16 + g) * HP + cq] = __floats2half2_rn(acc[g].x, acc[g].y);
        }
    }
    __syncthreads();

    // phase 5: out = vterm + hw @ Wp2^T + bp2*wsum
    {
        int c = t, g = c >> 4;
        float b = __ldg(&bp2[c]);
        float acc0 = S.vterm[c]           + b * S.wsum[g];
        float acc1 = S.vterm[256 + c]     + b * S.wsum[16 + g];
        float acc2 = S.vterm[512 + c]     + b * S.wsum[32 + g];
        float acc3 = S.vterm[768 + c]     + b * S.wsum[48 + g];

        const float4* wpt = (const float4*)&g_wp2t[c * C];
        const unsigned short* r0 = &S.hid[(g)      * HP];
        const unsigned short* r1 = &S.hid[(16 + g) * HP];
        const unsigned short* r2 = &S.hid[(32 + g) * HP];
        const unsigned short* r3 = &S.hid[(48 + g) * HP];
        #pragma unroll 8
        for (int kb = 0; kb < 64; kb++) {
            float4 wp = wpt[kb];
            uint2 u0 = *(const uint2*)&r0[kb * 4];
            uint2 u1 = *(const uint2*)&r1[kb * 4];
            uint2 u2 = *(const uint2*)&r2[kb * 4];
            uint2 u3 = *(const uint2*)&r3[kb * 4];
            float2 a0 = __half22float2(*(half2*)&u0.x), b0 = __half22float2(*(half2*)&u0.y);
            float2 a1 = __half22float2(*(half2*)&u1.x), b1 = __half22float2(*(half2*)&u1.y);
            float2 a2 = __half22float2(*(half2*)&u2.x), b2 = __half22float2(*(half2*)&u2.y);
            float2 a3 = __half22float2(*(half2*)&u3.x), b3 = __half22float2(*(half2*)&u3.y);
            acc0 = fmaf(wp.x, a0.x, acc0); acc0 = fmaf(wp.y, a0.y, acc0);
            acc0 = fmaf(wp.z, b0.x, acc0); acc0 = fmaf(wp.w, b0.y, acc0);
            acc1 = fmaf(wp.x, a1.x, acc1); acc1 = fmaf(wp.y, a1.y, acc1);
            acc1 = fmaf(wp.z, b1.x, acc1); acc1 = fmaf(wp.w, b1.y, acc1);
            acc2 = fmaf(wp.x, a2.x, acc2); acc2 = fmaf(wp.y, a2.y, acc2);
            acc2 = fmaf(wp.z, b2.x, acc2); acc2 = fmaf(wp.w, b2.y, acc2);
            acc3 = fmaf(wp.x, a3.x, acc3); acc3 = fmaf(wp.y, a3.y, acc3);
            acc3 = fmaf(wp.z, b3.x, acc3); acc3 = fmaf(wp.w, b3.y, acc3);
        }
        out[(n0 + 0) * C + c] = acc0;
        out[(n0 + 1) * C + c] = acc1;
        out[(n0 + 2) * C + c] = acc2;
        out[(n0 + 3) * C + c] = acc3;
    }
}

// ---------------- launch ----------------------------------------------------
extern "C" void kernel_launch(void* const* d_in, const int* in_sizes, int n_in,
                              void* d_out, int out_size) {
    (void)in_sizes; (void)n_in; (void)out_size;
    const float* feat  = (const float*)d_in[0];
    const float* coord = (const float*)d_in[1];
    const int*   knn   = (const int*)  d_in[2];
    const float* Wq = (const float*)d_in[3];  const float* bq = (const float*)d_in[4];  const float* bnq = (const float*)d_in[5];
    const float* Wk = (const float*)d_in[6];  const float* bk = (const float*)d_in[7];  const float* bnk = (const float*)d_in[8];
    const float* Wv = (const float*)d_in[9];  const float* bv = (const float*)d_in[10];
    const float* Wp1 = (const float*)d_in[11]; const float* bp1 = (const float*)d_in[12]; const float* bnp = (const float*)d_in[13];
    const float* Wp2 = (const float*)d_in[14]; const float* bp2 = (const float*)d_in[15];
    const float* Ww1 = (const float*)d_in[16]; const float* bw1 = (const float*)d_in[17]; const float* bnw = (const float*)d_in[18];
    const float* Ww2 = (const float*)d_in[19]; const float* bw2 = (const float*)d_in[20];
    float* out = (float*)d_out;

    int k1_smem = (BM * FS + BM * YS) * 4 + 4096 * 4;
    cudaFuncSetAttribute(k1_qkv,  cudaFuncAttributeMaxDynamicSharedMemorySize, k1_smem);
    cudaFuncSetAttribute(k2_attn, cudaFuncAttributeMaxDynamicSharedMemorySize, (int)sizeof(K2S));

    unsigned* wfrag;
    cudaGetSymbolAddress((void**)&wfrag, g_wfrag);

    prep_fold<<<1, 256>>>(bq, bnq, bk, bnk, bp1, bnp, bw1, bnw, bp2, Ww1);
    prep_wp2t<<<C, C>>>(Wp2);
    prep_afrag16<<<4, 256>>>(Wp2, Ww1);
    prep_w1frag<<<8, 256>>>(Ww1);
    prep_wfrag<<<32, 1024>>>(Wq, wfrag);
    prep_wfrag<<<32, 1024>>>(Wk, wfrag + 32 * 32 * 64);
    prep_wfrag<<<32, 1024>>>(Wv, wfrag + 2 * 32 * 32 * 64);
    k1_qkv<<<NPTS / BM, 256, k1_smem>>>(feat, bv);
    k2_attn<<<NPTS / P, 256, sizeof(K2S)>>>(coord, knn, Wp1, bp2, Ww2, bw2, out);
}